// round 1
// baseline (speedup 1.0000x reference)
#include <cuda_runtime.h>
#include <math.h>

#define kN   32768
#define kE   (kN * 16)
#define kD   256
#define kH   8
#define kDH  32
#define kTD  256
#define kFFN 1024
#define kL   2

// ---------------- device scratch (no runtime allocation allowed) ----------
__device__ float g_xn [kN * kD];
__device__ float g_q  [kN * kTD];
__device__ float g_k  [kN * kTD];
__device__ float g_v  [kN * kTD];
__device__ float g_agg[kN * kTD];
__device__ float g_ffn[kN * kFFN];
__device__ int   g_deg [kN];
__device__ int   g_fill[kN];
__device__ int   g_off [kN + 1];
__device__ int   g_csr [kE];

// ---------------- CSR build ----------------
__global__ void deg_count_kernel(const int* __restrict__ ei) {
    int e = blockIdx.x * 256 + threadIdx.x;
    if (e < kE) atomicAdd(&g_deg[ei[kE + e]], 1);
}

__global__ void prefix_kernel() {
    __shared__ int sums[1024];
    int t = threadIdx.x;
    int base = t * 32;
    int s = 0;
    #pragma unroll 4
    for (int i = 0; i < 32; ++i) s += g_deg[base + i];
    sums[t] = s;
    __syncthreads();
    for (int o = 1; o < 1024; o <<= 1) {
        int v = (t >= o) ? sums[t - o] : 0;
        __syncthreads();
        sums[t] += v;
        __syncthreads();
    }
    int run = sums[t] - s;  // exclusive prefix for this chunk
    for (int i = 0; i < 32; ++i) {
        g_off[base + i] = run;
        run += g_deg[base + i];
    }
    if (t == 1023) g_off[kN] = run;
}

__global__ void scatter_kernel(const int* __restrict__ ei) {
    int e = blockIdx.x * 256 + threadIdx.x;
    if (e < kE) {
        int d = ei[kE + e];
        int pos = g_off[d] + atomicAdd(&g_fill[d], 1);
        g_csr[pos] = ei[e];
    }
}

// ---------------- LayerNorm (one block of 256 per row) ----------------
__global__ void ln_kernel(const float* __restrict__ x, const float* __restrict__ g,
                          const float* __restrict__ b, float* __restrict__ y) {
    int t = threadIdx.x;
    int row = blockIdx.x;
    float v = x[(size_t)row * kD + t];
    __shared__ float sh[8];
    float s = v;
    #pragma unroll
    for (int o = 16; o; o >>= 1) s += __shfl_xor_sync(0xffffffffu, s, o);
    if ((t & 31) == 0) sh[t >> 5] = s;
    __syncthreads();
    float mean = (sh[0] + sh[1] + sh[2] + sh[3] + sh[4] + sh[5] + sh[6] + sh[7]) * (1.f / kD);
    float d = v - mean;
    float sq = d * d;
    __syncthreads();
    #pragma unroll
    for (int o = 16; o; o >>= 1) sq += __shfl_xor_sync(0xffffffffu, sq, o);
    if ((t & 31) == 0) sh[t >> 5] = sq;
    __syncthreads();
    float var = (sh[0] + sh[1] + sh[2] + sh[3] + sh[4] + sh[5] + sh[6] + sh[7]) * (1.f / kD);
    y[(size_t)row * kD + t] = d * rsqrtf(var + 1e-5f) * g[t] + b[t];
}

// ---------------- GEMM: C[M,N] = A[M,K] @ B[K,N] (+bias, gelu, residual) ----
// flags bit0: residual add into C ; bit1: exact gelu
__device__ __forceinline__ float gelu_exact(float x) {
    return 0.5f * x * (1.f + erff(x * 0.7071067811865475f));
}

__global__ void gemm64_kernel(const float* __restrict__ A, const float* __restrict__ B,
                              const float* __restrict__ bias, float* __restrict__ C,
                              int M, int N, int K, int flags) {
    __shared__ float As[16][64];
    __shared__ float Bs[16][68];
    int tid = threadIdx.x;
    int tx = tid & 15, ty = tid >> 4;
    int row0 = blockIdx.y << 6, col0 = blockIdx.x << 6;
    int ar = tid >> 2, ac = (tid & 3) << 2;
    int br = tid >> 4, bc = (tid & 15) << 2;
    const float* Aptr = A + (size_t)(row0 + ar) * K + ac;
    const float* Bptr = B + (size_t)br * N + col0 + bc;

    float acc[4][4] = {};
    for (int k0 = 0; k0 < K; k0 += 16) {
        float4 a4 = *reinterpret_cast<const float4*>(Aptr + k0);
        As[ac + 0][ar] = a4.x;
        As[ac + 1][ar] = a4.y;
        As[ac + 2][ar] = a4.z;
        As[ac + 3][ar] = a4.w;
        float4 b4 = *reinterpret_cast<const float4*>(Bptr + (size_t)k0 * N);
        *reinterpret_cast<float4*>(&Bs[br][bc]) = b4;
        __syncthreads();
        #pragma unroll
        for (int k = 0; k < 16; ++k) {
            float4 a = *reinterpret_cast<const float4*>(&As[k][ty << 2]);
            float4 b = *reinterpret_cast<const float4*>(&Bs[k][tx << 2]);
            acc[0][0] += a.x * b.x; acc[0][1] += a.x * b.y; acc[0][2] += a.x * b.z; acc[0][3] += a.x * b.w;
            acc[1][0] += a.y * b.x; acc[1][1] += a.y * b.y; acc[1][2] += a.y * b.z; acc[1][3] += a.y * b.w;
            acc[2][0] += a.z * b.x; acc[2][1] += a.z * b.y; acc[2][2] += a.z * b.z; acc[2][3] += a.z * b.w;
            acc[3][0] += a.w * b.x; acc[3][1] += a.w * b.y; acc[3][2] += a.w * b.z; acc[3][3] += a.w * b.w;
        }
        __syncthreads();
    }
    #pragma unroll
    for (int i = 0; i < 4; ++i) {
        int r = row0 + (ty << 2) + i;
        #pragma unroll
        for (int j = 0; j < 4; ++j) {
            int c = col0 + (tx << 2) + j;
            float vv = acc[i][j] + bias[c];
            if (flags & 2) vv = gelu_exact(vv);
            float* cp = C + (size_t)r * N + c;
            if (flags & 1) vv += *cp;
            *cp = vv;
        }
    }
}

// ---------------- Edge attention: one warp per (node, head) ---------------
__global__ void attn_kernel() {
    int gw = (blockIdx.x * blockDim.x + threadIdx.x) >> 5;
    int lane = threadIdx.x & 31;
    int node = gw >> 3;
    int head = gw & 7;
    if (node >= kN) return;
    int base = node * kTD + head * kDH + lane;
    int beg = g_off[node], end = g_off[node + 1];
    if (beg == end) {                 // original in-degree 0 -> masked to zero
        g_agg[base] = 0.f;
        return;
    }
    const float qv = g_q[base];
    float m = -INFINITY, l = 0.f, acc = 0.f;
    for (int i = beg - 1; i < end; ++i) {
        int src = (i < beg) ? node : g_csr[i];   // i==beg-1 is the self edge
        int sb = src * kTD + head * kDH + lane;
        float s = qv * g_k[sb];
        s += __shfl_xor_sync(0xffffffffu, s, 16);
        s += __shfl_xor_sync(0xffffffffu, s, 8);
        s += __shfl_xor_sync(0xffffffffu, s, 4);
        s += __shfl_xor_sync(0xffffffffu, s, 2);
        s += __shfl_xor_sync(0xffffffffu, s, 1);
        s *= 0.17677669529663687f;   // 1/sqrt(32)
        float mn = fmaxf(m, s);
        float corr = __expf(m - mn);
        float p = __expf(s - mn);
        l = l * corr + p;
        acc = acc * corr + p * g_v[sb];
        m = mn;
    }
    g_agg[base] = acc / l;
}

// ---------------- host orchestration ----------------
static inline void gemm(const float* A, const float* B, const float* bias, float* C,
                        int M, int N, int K, int flags) {
    dim3 g(N / 64, M / 64);
    gemm64_kernel<<<g, 256>>>(A, B, bias, C, M, N, K, flags);
}

extern "C" void kernel_launch(void* const* d_in, const int* in_sizes, int n_in,
                              void* d_out, int out_size) {
    const float* x     = (const float*)d_in[0];
    const int*   ei    = (const int*)  d_in[1];
    const float* w_in  = (const float*)d_in[2];
    const float* b_in  = (const float*)d_in[3];
    const float* ln1_g = (const float*)d_in[4];
    const float* ln1_b = (const float*)d_in[5];
    const float* ln2_g = (const float*)d_in[6];
    const float* ln2_b = (const float*)d_in[7];
    const float* wq = (const float*)d_in[8];  const float* bq = (const float*)d_in[9];
    const float* wk = (const float*)d_in[10]; const float* bk = (const float*)d_in[11];
    const float* wv = (const float*)d_in[12]; const float* bv = (const float*)d_in[13];
    const float* wo = (const float*)d_in[14]; const float* bo = (const float*)d_in[15];
    const float* w1 = (const float*)d_in[16]; const float* b1 = (const float*)d_in[17];
    const float* w2 = (const float*)d_in[18]; const float* b2 = (const float*)d_in[19];
    float* h = (float*)d_out;

    float *xn, *q, *k, *v, *agg, *ffn;
    int *deg, *fill;
    cudaGetSymbolAddress((void**)&xn,  g_xn);
    cudaGetSymbolAddress((void**)&q,   g_q);
    cudaGetSymbolAddress((void**)&k,   g_k);
    cudaGetSymbolAddress((void**)&v,   g_v);
    cudaGetSymbolAddress((void**)&agg, g_agg);
    cudaGetSymbolAddress((void**)&ffn, g_ffn);
    cudaGetSymbolAddress((void**)&deg,  g_deg);
    cudaGetSymbolAddress((void**)&fill, g_fill);

    // ---- CSR by dst (rebuilt every call; deterministic inputs) ----
    cudaMemsetAsync(deg,  0, kN * sizeof(int));
    cudaMemsetAsync(fill, 0, kN * sizeof(int));
    deg_count_kernel<<<kE / 256, 256>>>(ei);
    prefix_kernel<<<1, 1024>>>();
    scatter_kernel<<<kE / 256, 256>>>(ei);

    // ---- input projection: h = x @ w_in + b_in ----
    gemm(x, w_in, b_in, h, kN, kD, kD, 0);

    for (int l = 0; l < kL; ++l) {
        const float* Wq = wq + (size_t)l * kD * kTD;
        const float* Wk = wk + (size_t)l * kD * kTD;
        const float* Wv = wv + (size_t)l * kD * kTD;
        const float* Wo = wo + (size_t)l * kTD * kD;
        const float* W1 = w1 + (size_t)l * kD * kFFN;
        const float* W2 = w2 + (size_t)l * kFFN * kD;

        ln_kernel<<<kN, 256>>>(h, ln1_g + l * kD, ln1_b + l * kD, xn);
        gemm(xn, Wq, bq + (size_t)l * kTD, q, kN, kTD, kD, 0);
        gemm(xn, Wk, bk + (size_t)l * kTD, k, kN, kTD, kD, 0);
        gemm(xn, Wv, bv + (size_t)l * kTD, v, kN, kTD, kD, 0);

        attn_kernel<<<kN, 256>>>();   // one warp per (node, head)

        gemm(agg, Wo, bo + (size_t)l * kD, h, kN, kD, kTD, 1);  // h += agg@wo + bo

        ln_kernel<<<kN, 256>>>(h, ln2_g + l * kD, ln2_b + l * kD, xn);
        gemm(xn, W1, b1 + (size_t)l * kFFN, ffn, kN, kFFN, kD, 2);  // gelu
        gemm(ffn, W2, b2 + (size_t)l * kD, h, kN, kD, kFFN, 1);     // h += ffn@w2 + b2
    }
}

// round 2
// speedup vs baseline: 1.1755x; 1.1755x over previous
#include <cuda_runtime.h>
#include <math.h>

#define kN   32768
#define kE   (kN * 16)
#define kD   256
#define kH   8
#define kDH  32
#define kTD  256
#define kFFN 1024
#define kL   2

// ---------------- device scratch (no runtime allocation allowed) ----------
__device__ float g_xn [kN * kD];
__device__ float g_q  [kN * kTD];
__device__ float g_k  [kN * kTD];
__device__ float g_v  [kN * kTD];
__device__ float g_agg[kN * kTD];
__device__ float g_ffn[kN * kFFN];
__device__ int   g_deg [kN];
__device__ int   g_fill[kN];
__device__ int   g_off [kN + 1];
__device__ int   g_csr [kE];

// ---------------- CSR build ----------------
__global__ void deg_count_kernel(const int* __restrict__ ei) {
    int e = blockIdx.x * 256 + threadIdx.x;
    if (e < kE) atomicAdd(&g_deg[ei[kE + e]], 1);
}

__global__ void prefix_kernel() {
    __shared__ int sums[1024];
    int t = threadIdx.x;
    int base = t * 32;
    int s = 0;
    #pragma unroll 4
    for (int i = 0; i < 32; ++i) s += g_deg[base + i];
    sums[t] = s;
    __syncthreads();
    for (int o = 1; o < 1024; o <<= 1) {
        int v = (t >= o) ? sums[t - o] : 0;
        __syncthreads();
        sums[t] += v;
        __syncthreads();
    }
    int run = sums[t] - s;  // exclusive prefix for this chunk
    for (int i = 0; i < 32; ++i) {
        g_off[base + i] = run;
        run += g_deg[base + i];
    }
    if (t == 1023) g_off[kN] = run;
}

__global__ void scatter_kernel(const int* __restrict__ ei) {
    int e = blockIdx.x * 256 + threadIdx.x;
    if (e < kE) {
        int d = ei[kE + e];
        int pos = g_off[d] + atomicAdd(&g_fill[d], 1);
        g_csr[pos] = ei[e];
    }
}

// ---------------- LayerNorm (one block of 256 per row) ----------------
__global__ void ln_kernel(const float* __restrict__ x, const float* __restrict__ g,
                          const float* __restrict__ b, float* __restrict__ y) {
    int t = threadIdx.x;
    int row = blockIdx.x;
    float v = x[(size_t)row * kD + t];
    __shared__ float sh[8];
    float s = v;
    #pragma unroll
    for (int o = 16; o; o >>= 1) s += __shfl_xor_sync(0xffffffffu, s, o);
    if ((t & 31) == 0) sh[t >> 5] = s;
    __syncthreads();
    float mean = (sh[0] + sh[1] + sh[2] + sh[3] + sh[4] + sh[5] + sh[6] + sh[7]) * (1.f / kD);
    float d = v - mean;
    float sq = d * d;
    __syncthreads();
    #pragma unroll
    for (int o = 16; o; o >>= 1) sq += __shfl_xor_sync(0xffffffffu, sq, o);
    if ((t & 31) == 0) sh[t >> 5] = sq;
    __syncthreads();
    float var = (sh[0] + sh[1] + sh[2] + sh[3] + sh[4] + sh[5] + sh[6] + sh[7]) * (1.f / kD);
    y[(size_t)row * kD + t] = d * rsqrtf(var + 1e-5f) * g[t] + b[t];
}

// ---------------- GEMM: C[M,N] = A[M,K] @ B[K,N] (+bias, gelu, residual) ----
// flags bit0: residual add into C ; bit1: exact gelu
__device__ __forceinline__ float gelu_exact(float x) {
    return 0.5f * x * (1.f + erff(x * 0.7071067811865475f));
}

// 128x128 block, 8x8 micro-tile (split 4+4 rows/cols), K-step 8.
__global__ void __launch_bounds__(256, 2)
gemm128_kernel(const float* __restrict__ A, const float* __restrict__ B,
               const float* __restrict__ bias, float* __restrict__ C,
               int M, int N, int K, int flags) {
    __shared__ float As[8][128];
    __shared__ float Bs[8][128];
    int tid = threadIdx.x;
    int tx4 = (tid & 15) << 2;      // col frag base (0..60)
    int ty4 = (tid >> 4) << 2;      // row frag base (0..60)
    int row0 = blockIdx.y << 7, col0 = blockIdx.x << 7;

    // A tile load: 128 rows x 8 cols, one float4 per thread
    int arow = tid >> 1;
    int acol = (tid & 1) << 2;
    // B tile load: 8 rows x 128 cols, one float4 per thread
    int brow = tid >> 5;
    int bcol = (tid & 31) << 2;
    const float* Aptr = A + (size_t)(row0 + arow) * K + acol;
    const float* Bptr = B + (size_t)brow * N + col0 + bcol;

    float acc[8][8] = {};
    for (int k0 = 0; k0 < K; k0 += 8) {
        float4 a4 = *reinterpret_cast<const float4*>(Aptr + k0);
        float4 b4 = *reinterpret_cast<const float4*>(Bptr + (size_t)k0 * N);
        As[acol + 0][arow] = a4.x;
        As[acol + 1][arow] = a4.y;
        As[acol + 2][arow] = a4.z;
        As[acol + 3][arow] = a4.w;
        *reinterpret_cast<float4*>(&Bs[brow][bcol]) = b4;
        __syncthreads();
        #pragma unroll
        for (int k = 0; k < 8; ++k) {
            float4 a0 = *reinterpret_cast<const float4*>(&As[k][ty4]);
            float4 a1 = *reinterpret_cast<const float4*>(&As[k][ty4 + 64]);
            float4 b0 = *reinterpret_cast<const float4*>(&Bs[k][tx4]);
            float4 b1 = *reinterpret_cast<const float4*>(&Bs[k][tx4 + 64]);
            float av[8] = {a0.x, a0.y, a0.z, a0.w, a1.x, a1.y, a1.z, a1.w};
            float bv[8] = {b0.x, b0.y, b0.z, b0.w, b1.x, b1.y, b1.z, b1.w};
            #pragma unroll
            for (int i = 0; i < 8; ++i)
                #pragma unroll
                for (int j = 0; j < 8; ++j)
                    acc[i][j] += av[i] * bv[j];
        }
        __syncthreads();
    }

    // Epilogue: rows {row0+ty4+i, row0+64+ty4+i}, cols {col0+tx4+j, col0+64+tx4+j}
    #pragma unroll
    for (int ib = 0; ib < 2; ++ib) {
        #pragma unroll
        for (int i = 0; i < 4; ++i) {
            int r = row0 + ib * 64 + ty4 + i;
            #pragma unroll
            for (int jb = 0; jb < 2; ++jb) {
                int c = col0 + jb * 64 + tx4;
                float4 bs = *reinterpret_cast<const float4*>(&bias[c]);
                float v0 = acc[ib * 4 + i][jb * 4 + 0] + bs.x;
                float v1 = acc[ib * 4 + i][jb * 4 + 1] + bs.y;
                float v2 = acc[ib * 4 + i][jb * 4 + 2] + bs.z;
                float v3 = acc[ib * 4 + i][jb * 4 + 3] + bs.w;
                if (flags & 2) {
                    v0 = gelu_exact(v0); v1 = gelu_exact(v1);
                    v2 = gelu_exact(v2); v3 = gelu_exact(v3);
                }
                float4* cp = reinterpret_cast<float4*>(C + (size_t)r * N + c);
                if (flags & 1) {
                    float4 old = *cp;
                    v0 += old.x; v1 += old.y; v2 += old.z; v3 += old.w;
                }
                float4 out = {v0, v1, v2, v3};
                *cp = out;
            }
        }
    }
}

// ---------------- Edge attention: one warp per (node, head) ---------------
__global__ void attn_kernel() {
    int gw = (blockIdx.x * blockDim.x + threadIdx.x) >> 5;
    int lane = threadIdx.x & 31;
    int node = gw >> 3;
    int head = gw & 7;
    if (node >= kN) return;
    int base = node * kTD + head * kDH + lane;
    int beg = g_off[node], end = g_off[node + 1];
    if (beg == end) {                 // original in-degree 0 -> masked to zero
        g_agg[base] = 0.f;
        return;
    }
    const float qv = g_q[base];
    float m = -INFINITY, l = 0.f, acc = 0.f;
    for (int i = beg - 1; i < end; ++i) {
        int src = (i < beg) ? node : g_csr[i];   // i==beg-1 is the self edge
        int sb = src * kTD + head * kDH + lane;
        float s = qv * g_k[sb];
        s += __shfl_xor_sync(0xffffffffu, s, 16);
        s += __shfl_xor_sync(0xffffffffu, s, 8);
        s += __shfl_xor_sync(0xffffffffu, s, 4);
        s += __shfl_xor_sync(0xffffffffu, s, 2);
        s += __shfl_xor_sync(0xffffffffu, s, 1);
        s *= 0.17677669529663687f;   // 1/sqrt(32)
        float mn = fmaxf(m, s);
        float corr = __expf(m - mn);
        float p = __expf(s - mn);
        l = l * corr + p;
        acc = acc * corr + p * g_v[sb];
        m = mn;
    }
    g_agg[base] = acc / l;
}

// ---------------- host orchestration ----------------
static inline void gemm(const float* A, const float* B, const float* bias, float* C,
                        int M, int N, int K, int flags) {
    dim3 g(N / 128, M / 128);
    gemm128_kernel<<<g, 256>>>(A, B, bias, C, M, N, K, flags);
}

extern "C" void kernel_launch(void* const* d_in, const int* in_sizes, int n_in,
                              void* d_out, int out_size) {
    const float* x     = (const float*)d_in[0];
    const int*   ei    = (const int*)  d_in[1];
    const float* w_in  = (const float*)d_in[2];
    const float* b_in  = (const float*)d_in[3];
    const float* ln1_g = (const float*)d_in[4];
    const float* ln1_b = (const float*)d_in[5];
    const float* ln2_g = (const float*)d_in[6];
    const float* ln2_b = (const float*)d_in[7];
    const float* wq = (const float*)d_in[8];  const float* bq = (const float*)d_in[9];
    const float* wk = (const float*)d_in[10]; const float* bk = (const float*)d_in[11];
    const float* wv = (const float*)d_in[12]; const float* bv = (const float*)d_in[13];
    const float* wo = (const float*)d_in[14]; const float* bo = (const float*)d_in[15];
    const float* w1 = (const float*)d_in[16]; const float* b1 = (const float*)d_in[17];
    const float* w2 = (const float*)d_in[18]; const float* b2 = (const float*)d_in[19];
    float* h = (float*)d_out;

    float *xn, *q, *k, *v, *agg, *ffn;
    int *deg, *fill;
    cudaGetSymbolAddress((void**)&xn,  g_xn);
    cudaGetSymbolAddress((void**)&q,   g_q);
    cudaGetSymbolAddress((void**)&k,   g_k);
    cudaGetSymbolAddress((void**)&v,   g_v);
    cudaGetSymbolAddress((void**)&agg, g_agg);
    cudaGetSymbolAddress((void**)&ffn, g_ffn);
    cudaGetSymbolAddress((void**)&deg,  g_deg);
    cudaGetSymbolAddress((void**)&fill, g_fill);

    // ---- CSR by dst (rebuilt every call; deterministic inputs) ----
    cudaMemsetAsync(deg,  0, kN * sizeof(int));
    cudaMemsetAsync(fill, 0, kN * sizeof(int));
    deg_count_kernel<<<kE / 256, 256>>>(ei);
    prefix_kernel<<<1, 1024>>>();
    scatter_kernel<<<kE / 256, 256>>>(ei);

    // ---- input projection: h = x @ w_in + b_in ----
    gemm(x, w_in, b_in, h, kN, kD, kD, 0);

    for (int l = 0; l < kL; ++l) {
        const float* Wq = wq + (size_t)l * kD * kTD;
        const float* Wk = wk + (size_t)l * kD * kTD;
        const float* Wv = wv + (size_t)l * kD * kTD;
        const float* Wo = wo + (size_t)l * kTD * kD;
        const float* W1 = w1 + (size_t)l * kD * kFFN;
        const float* W2 = w2 + (size_t)l * kFFN * kD;

        ln_kernel<<<kN, 256>>>(h, ln1_g + l * kD, ln1_b + l * kD, xn);
        gemm(xn, Wq, bq + (size_t)l * kTD, q, kN, kTD, kD, 0);
        gemm(xn, Wk, bk + (size_t)l * kTD, k, kN, kTD, kD, 0);
        gemm(xn, Wv, bv + (size_t)l * kTD, v, kN, kTD, kD, 0);

        attn_kernel<<<kN, 256>>>();   // one warp per (node, head)

        gemm(agg, Wo, bo + (size_t)l * kD, h, kN, kD, kTD, 1);  // h += agg@wo + bo

        ln_kernel<<<kN, 256>>>(h, ln2_g + l * kD, ln2_b + l * kD, xn);
        gemm(xn, W1, b1 + (size_t)l * kFFN, ffn, kN, kFFN, kD, 2);  // gelu
        gemm(ffn, W2, b2 + (size_t)l * kD, h, kN, kD, kFFN, 1);     // h += ffn@w2 + b2
    }
}

// round 4
// speedup vs baseline: 1.4061x; 1.1962x over previous
#include <cuda_runtime.h>
#include <math.h>
#include <stdint.h>

#define kN   32768
#define kE   (kN * 16)
#define kD   256
#define kH   8
#define kDH  32
#define kTD  256
#define kFFN 1024
#define kL   2
#define kQKV 768

// ---------------- device scratch ----------------
__device__ float g_xn  [kN * kD];
__device__ float g_qkv [kN * kQKV];
__device__ float g_agg [kN * kTD];
__device__ float g_ffn [kN * kFFN];
__device__ float g_wqkvT[kL * kQKV * kD];
__device__ float g_woT  [kL * kD * kTD];
__device__ float g_w1T  [kL * kFFN * kD];
__device__ float g_w2T  [kL * kD * kFFN];
__device__ float g_bqkv [kL * kQKV];
__device__ int   g_deg [kN];
__device__ int   g_fill[kN];
__device__ int   g_off [kN + 1];
__device__ int   g_csr [kE];

// ---------------- tf32 helpers ----------------
__device__ __forceinline__ uint32_t to_tf32(float x) {
    uint32_t r;
    asm("cvt.rna.tf32.f32 %0, %1;" : "=r"(r) : "f"(x));
    return r;
}
__device__ __forceinline__ void mma_tf32(float& d0, float& d1, float& d2, float& d3,
                                         uint32_t a0, uint32_t a1, uint32_t a2, uint32_t a3,
                                         uint32_t b0, uint32_t b1) {
    asm volatile("mma.sync.aligned.m16n8k8.row.col.f32.tf32.tf32.f32 "
                 "{%0,%1,%2,%3}, {%4,%5,%6,%7}, {%8,%9}, {%0,%1,%2,%3};"
                 : "+f"(d0), "+f"(d1), "+f"(d2), "+f"(d3)
                 : "r"(a0), "r"(a1), "r"(a2), "r"(a3), "r"(b0), "r"(b1));
}

__device__ __forceinline__ float gelu_exact(float x) {
    return 0.5f * x * (1.f + erff(x * 0.7071067811865475f));
}

// ---------------- tf32 mma.sync GEMM: C[M,N] = A[M,K] @ Bt[N,K]^T ---------
// Block 128x128, 8 warps (2x4), warp tile 64x32, BK=32.
// Smem fragment-ordered: As[kc][mt][reg(4)][lane(32)], Bs[kc][nt][reg(2)][lane(32)]
#define BM 128
#define BN 128
#define BK 32

__global__ void __launch_bounds__(256, 1)
gemm_tc(const float* __restrict__ A, const float* __restrict__ Bt,
        const float* __restrict__ bias, float* __restrict__ C,
        int M, int N, int K, int flags) {
    __shared__ uint32_t As[4][8][4][32];   // 16 KB
    __shared__ uint32_t Bs[4][16][2][32];  // 16 KB

    int tid = threadIdx.x;
    int wid = tid >> 5;
    int lane = tid & 31;
    int warp_row = wid >> 2;       // 0..1
    int warp_col = wid & 3;        // 0..3
    int row0 = blockIdx.y * BM, col0 = blockIdx.x * BN;

    const float* Ag = A + (size_t)row0 * K;
    const float* Bg = Bt + (size_t)col0 * K;

    float acc[4][4][4];
    #pragma unroll
    for (int i = 0; i < 4; ++i)
        #pragma unroll
        for (int j = 0; j < 4; ++j)
            #pragma unroll
            for (int q = 0; q < 4; ++q) acc[i][j][q] = 0.f;

    int nIter = K / BK;
    float4 pa[4], pb[4];

    // prologue: prefetch stage 0
    #pragma unroll
    for (int j = 0; j < 4; ++j) {
        int idx = tid + j * 256;
        int r = idx >> 3, c4 = idx & 7;
        pa[j] = *reinterpret_cast<const float4*>(Ag + (size_t)r * K + c4 * 4);
        pb[j] = *reinterpret_cast<const float4*>(Bg + (size_t)r * K + c4 * 4);
    }

    for (int it = 0; it < nIter; ++it) {
        // store prefetched stage to smem (fragment-ordered, tf32-converted)
        #pragma unroll
        for (int j = 0; j < 4; ++j) {
            int idx = tid + j * 256;
            int r = idx >> 3, c4 = idx & 7;
            int kc = c4 >> 1, chalf = c4 & 1;
            int areg = ((r >> 3) & 1) + 2 * chalf;
            uint32_t* ap = &As[kc][r >> 4][areg][(r & 7) * 4];
            ap[0] = to_tf32(pa[j].x); ap[1] = to_tf32(pa[j].y);
            ap[2] = to_tf32(pa[j].z); ap[3] = to_tf32(pa[j].w);
            uint32_t* bp = &Bs[kc][r >> 3][chalf][(r & 7) * 4];
            bp[0] = to_tf32(pb[j].x); bp[1] = to_tf32(pb[j].y);
            bp[2] = to_tf32(pb[j].z); bp[3] = to_tf32(pb[j].w);
        }
        __syncthreads();

        // prefetch next stage
        if (it + 1 < nIter) {
            int kk = (it + 1) * BK;
            #pragma unroll
            for (int j = 0; j < 4; ++j) {
                int idx = tid + j * 256;
                int r = idx >> 3, c4 = idx & 7;
                pa[j] = *reinterpret_cast<const float4*>(Ag + (size_t)r * K + kk + c4 * 4);
                pb[j] = *reinterpret_cast<const float4*>(Bg + (size_t)r * K + kk + c4 * 4);
            }
        }

        // compute
        #pragma unroll
        for (int kc = 0; kc < 4; ++kc) {
            uint32_t af[4][4], bf[4][2];
            #pragma unroll
            for (int mt = 0; mt < 4; ++mt) {
                int mtg = warp_row * 4 + mt;
                af[mt][0] = As[kc][mtg][0][lane];
                af[mt][1] = As[kc][mtg][1][lane];
                af[mt][2] = As[kc][mtg][2][lane];
                af[mt][3] = As[kc][mtg][3][lane];
            }
            #pragma unroll
            for (int nt = 0; nt < 4; ++nt) {
                int ntg = warp_col * 4 + nt;
                bf[nt][0] = Bs[kc][ntg][0][lane];
                bf[nt][1] = Bs[kc][ntg][1][lane];
            }
            #pragma unroll
            for (int mt = 0; mt < 4; ++mt)
                #pragma unroll
                for (int nt = 0; nt < 4; ++nt)
                    mma_tf32(acc[mt][nt][0], acc[mt][nt][1], acc[mt][nt][2], acc[mt][nt][3],
                             af[mt][0], af[mt][1], af[mt][2], af[mt][3],
                             bf[nt][0], bf[nt][1]);
        }
        __syncthreads();
    }

    // epilogue
    int g = lane >> 2, tg = lane & 3;
    #pragma unroll
    for (int mt = 0; mt < 4; ++mt) {
        int rbase = row0 + warp_row * 64 + mt * 16 + g;
        #pragma unroll
        for (int nt = 0; nt < 4; ++nt) {
            int c = col0 + warp_col * 32 + nt * 8 + tg * 2;
            float2 bs = *reinterpret_cast<const float2*>(&bias[c]);
            float v0 = acc[mt][nt][0] + bs.x;
            float v1 = acc[mt][nt][1] + bs.y;
            float v2 = acc[mt][nt][2] + bs.x;
            float v3 = acc[mt][nt][3] + bs.y;
            if (flags & 2) { v0 = gelu_exact(v0); v1 = gelu_exact(v1); v2 = gelu_exact(v2); v3 = gelu_exact(v3); }
            float2* cp0 = reinterpret_cast<float2*>(C + (size_t)rbase * N + c);
            float2* cp1 = reinterpret_cast<float2*>(C + (size_t)(rbase + 8) * N + c);
            if (flags & 1) {
                float2 o0 = *cp0, o1 = *cp1;
                v0 += o0.x; v1 += o0.y; v2 += o1.x; v3 += o1.y;
            }
            float2 r0 = {v0, v1}, r1 = {v2, v3};
            *cp0 = r0;
            *cp1 = r1;
        }
    }
}

// ---------------- weight transpose: dst[C][R] = src[R][C]^T ----------------
__global__ void transpose_kernel(const float* __restrict__ src, float* __restrict__ dst,
                                 int R, int C) {
    __shared__ float t[32][33];
    int bx = blockIdx.x * 32, by = blockIdx.y * 32;
    int x = bx + threadIdx.x;
    #pragma unroll
    for (int j = 0; j < 32; j += 8)
        t[threadIdx.y + j][threadIdx.x] = src[(size_t)(by + threadIdx.y + j) * C + x];
    __syncthreads();
    int xo = by + threadIdx.x;
    #pragma unroll
    for (int j = 0; j < 32; j += 8)
        dst[(size_t)(bx + threadIdx.y + j) * R + xo] = t[threadIdx.x][threadIdx.y + j];
}

// ---------------- CSR build ----------------
__global__ void deg_count_kernel(const int* __restrict__ ei) {
    int e = blockIdx.x * 256 + threadIdx.x;
    if (e < kE) atomicAdd(&g_deg[ei[kE + e]], 1);
}
__global__ void prefix_kernel() {
    __shared__ int sums[1024];
    int t = threadIdx.x;
    int base = t * 32;
    int s = 0;
    #pragma unroll 4
    for (int i = 0; i < 32; ++i) s += g_deg[base + i];
    sums[t] = s;
    __syncthreads();
    for (int o = 1; o < 1024; o <<= 1) {
        int v = (t >= o) ? sums[t - o] : 0;
        __syncthreads();
        sums[t] += v;
        __syncthreads();
    }
    int run = sums[t] - s;
    for (int i = 0; i < 32; ++i) { g_off[base + i] = run; run += g_deg[base + i]; }
    if (t == 1023) g_off[kN] = run;
}
__global__ void scatter_kernel(const int* __restrict__ ei) {
    int e = blockIdx.x * 256 + threadIdx.x;
    if (e < kE) {
        int d = ei[kE + e];
        int pos = g_off[d] + atomicAdd(&g_fill[d], 1);
        g_csr[pos] = ei[e];
    }
}

// ---------------- LayerNorm ----------------
__global__ void ln_kernel(const float* __restrict__ x, const float* __restrict__ g,
                          const float* __restrict__ b, float* __restrict__ y) {
    int t = threadIdx.x;
    int row = blockIdx.x;
    float v = x[(size_t)row * kD + t];
    __shared__ float sh[8];
    float s = v;
    #pragma unroll
    for (int o = 16; o; o >>= 1) s += __shfl_xor_sync(0xffffffffu, s, o);
    if ((t & 31) == 0) sh[t >> 5] = s;
    __syncthreads();
    float mean = (sh[0]+sh[1]+sh[2]+sh[3]+sh[4]+sh[5]+sh[6]+sh[7]) * (1.f / kD);
    float d = v - mean;
    float sq = d * d;
    __syncthreads();
    #pragma unroll
    for (int o = 16; o; o >>= 1) sq += __shfl_xor_sync(0xffffffffu, sq, o);
    if ((t & 31) == 0) sh[t >> 5] = sq;
    __syncthreads();
    float var = (sh[0]+sh[1]+sh[2]+sh[3]+sh[4]+sh[5]+sh[6]+sh[7]) * (1.f / kD);
    y[(size_t)row * kD + t] = d * rsqrtf(var + 1e-5f) * g[t] + b[t];
}

// ---------------- Edge attention (q,k,v packed stride 768) ----------------
__global__ void attn_kernel() {
    int gw = (blockIdx.x * blockDim.x + threadIdx.x) >> 5;
    int lane = threadIdx.x & 31;
    int node = gw >> 3;
    int head = gw & 7;
    if (node >= kN) return;
    int hd = head * kDH + lane;
    int beg = g_off[node], end = g_off[node + 1];
    if (beg == end) { g_agg[node * kTD + hd] = 0.f; return; }
    const float qv = g_qkv[node * kQKV + hd];
    float m = -INFINITY, l = 0.f, acc = 0.f;
    for (int i = beg - 1; i < end; ++i) {
        int src = (i < beg) ? node : g_csr[i];
        int sb = src * kQKV + hd;
        float s = qv * g_qkv[sb + 256];
        s += __shfl_xor_sync(0xffffffffu, s, 16);
        s += __shfl_xor_sync(0xffffffffu, s, 8);
        s += __shfl_xor_sync(0xffffffffu, s, 4);
        s += __shfl_xor_sync(0xffffffffu, s, 2);
        s += __shfl_xor_sync(0xffffffffu, s, 1);
        s *= 0.17677669529663687f;
        float mn = fmaxf(m, s);
        float corr = __expf(m - mn);
        float p = __expf(s - mn);
        l = l * corr + p;
        acc = acc * corr + p * g_qkv[sb + 512];
        m = mn;
    }
    g_agg[node * kTD + hd] = acc / l;
}

// ---------------- host orchestration ----------------
static inline void gemm(const float* A, const float* Bt, const float* bias, float* C,
                        int M, int N, int K, int flags) {
    dim3 g(N / BN, M / BM);
    gemm_tc<<<g, 256>>>(A, Bt, bias, C, M, N, K, flags);
}
static inline void transpose(const float* src, float* dst, int R, int C) {
    dim3 g(C / 32, R / 32), b(32, 8);
    transpose_kernel<<<g, b>>>(src, dst, R, C);
}

extern "C" void kernel_launch(void* const* d_in, const int* in_sizes, int n_in,
                              void* d_out, int out_size) {
    const float* x     = (const float*)d_in[0];
    const int*   ei    = (const int*)  d_in[1];
    const float* w_in  = (const float*)d_in[2];
    const float* b_in  = (const float*)d_in[3];
    const float* ln1_g = (const float*)d_in[4];
    const float* ln1_b = (const float*)d_in[5];
    const float* ln2_g = (const float*)d_in[6];
    const float* ln2_b = (const float*)d_in[7];
    const float* wq = (const float*)d_in[8];  const float* bq = (const float*)d_in[9];
    const float* wk = (const float*)d_in[10]; const float* bk = (const float*)d_in[11];
    const float* wv = (const float*)d_in[12]; const float* bv = (const float*)d_in[13];
    const float* wo = (const float*)d_in[14]; const float* bo = (const float*)d_in[15];
    const float* w1 = (const float*)d_in[16]; const float* b1 = (const float*)d_in[17];
    const float* w2 = (const float*)d_in[18]; const float* b2 = (const float*)d_in[19];
    float* h = (float*)d_out;

    float *xn, *qkv, *agg, *ffn, *wqkvT, *woT, *w1T, *w2T, *bqkv;
    int *deg, *fill;
    cudaGetSymbolAddress((void**)&xn,    g_xn);
    cudaGetSymbolAddress((void**)&qkv,   g_qkv);
    cudaGetSymbolAddress((void**)&agg,   g_agg);
    cudaGetSymbolAddress((void**)&ffn,   g_ffn);
    cudaGetSymbolAddress((void**)&wqkvT, g_wqkvT);
    cudaGetSymbolAddress((void**)&woT,   g_woT);
    cudaGetSymbolAddress((void**)&w1T,   g_w1T);
    cudaGetSymbolAddress((void**)&w2T,   g_w2T);
    cudaGetSymbolAddress((void**)&bqkv,  g_bqkv);
    cudaGetSymbolAddress((void**)&deg,   g_deg);
    cudaGetSymbolAddress((void**)&fill,  g_fill);

    // ---- CSR by dst ----
    cudaMemsetAsync(deg,  0, kN * sizeof(int));
    cudaMemsetAsync(fill, 0, kN * sizeof(int));
    deg_count_kernel<<<kE / 256, 256>>>(ei);
    prefix_kernel<<<1, 1024>>>();
    scatter_kernel<<<kE / 256, 256>>>(ei);

    // ---- weight transposes + bias packing ----
    transpose(w_in, xn, kD, kD);   // xn[0:65536] = w_inT (consumed before LN writes)
    for (int l = 0; l < kL; ++l) {
        transpose(wq + (size_t)l * kD * kTD, wqkvT + (size_t)l * kQKV * kD + 0 * kTD * kD, kD, kTD);
        transpose(wk + (size_t)l * kD * kTD, wqkvT + (size_t)l * kQKV * kD + 1 * kTD * kD, kD, kTD);
        transpose(wv + (size_t)l * kD * kTD, wqkvT + (size_t)l * kQKV * kD + 2 * kTD * kD, kD, kTD);
        transpose(wo + (size_t)l * kTD * kD, woT + (size_t)l * kD * kTD, kTD, kD);
        transpose(w1 + (size_t)l * kD * kFFN, w1T + (size_t)l * kFFN * kD, kD, kFFN);
        transpose(w2 + (size_t)l * kFFN * kD, w2T + (size_t)l * kD * kFFN, kFFN, kD);
        cudaMemcpyAsync(bqkv + (size_t)l * kQKV + 0,   bq + (size_t)l * kTD, kTD * 4, cudaMemcpyDeviceToDevice);
        cudaMemcpyAsync(bqkv + (size_t)l * kQKV + 256, bk + (size_t)l * kTD, kTD * 4, cudaMemcpyDeviceToDevice);
        cudaMemcpyAsync(bqkv + (size_t)l * kQKV + 512, bv + (size_t)l * kTD, kTD * 4, cudaMemcpyDeviceToDevice);
    }

    // ---- input projection: h = x @ w_in + b_in  (w_inT staged in xn) ----
    gemm(x, xn, b_in, h, kN, kD, kD, 0);

    for (int l = 0; l < kL; ++l) {
        ln_kernel<<<kN, 256>>>(h, ln1_g + l * kD, ln1_b + l * kD, xn);
        gemm(xn, wqkvT + (size_t)l * kQKV * kD, bqkv + (size_t)l * kQKV, qkv, kN, kQKV, kD, 0);
        attn_kernel<<<kN, 256>>>();
        gemm(agg, woT + (size_t)l * kD * kTD, bo + (size_t)l * kD, h, kN, kD, kTD, 1);
        ln_kernel<<<kN, 256>>>(h, ln2_g + l * kD, ln2_b + l * kD, xn);
        gemm(xn, w1T + (size_t)l * kFFN * kD, b1 + (size_t)l * kFFN, ffn, kN, kFFN, kD, 2);
        gemm(ffn, w2T + (size_t)l * kD * kFFN, b2 + (size_t)l * kD, h, kN, kD, kFFN, 1);
    }
}

// round 5
// speedup vs baseline: 2.4454x; 1.7392x over previous
#include <cuda_runtime.h>
#include <cuda_fp16.h>
#include <math.h>
#include <stdint.h>

#define kN   32768
#define kE   (kN * 16)
#define kD   256
#define kH   8
#define kDH  32
#define kTD  256
#define kFFN 1024
#define kL   2
#define kQKV 768

// ---------------- device scratch ----------------
__device__ float g_xn  [kN * kD];
__device__ float g_qkv [kN * kQKV];
__device__ float g_agg [kN * kTD];
__device__ float g_ffn [kN * kFFN];
__device__ float g_wqkvT[kL * kQKV * kD];
__device__ float g_woT  [kL * kD * kTD];
__device__ float g_w1T  [kL * kFFN * kD];
__device__ float g_w2T  [kL * kD * kFFN];
__device__ float g_bqkv [kL * kQKV];
__device__ int   g_deg [kN];
__device__ int   g_fill[kN];
__device__ int   g_off [kN + 1];
__device__ int   g_csr [kE];

// ---------------- fp16 helpers ----------------
__device__ __forceinline__ uint32_t pack_h2(float lo, float hi) {
    __half2 h = __floats2half2_rn(lo, hi);
    return *reinterpret_cast<uint32_t*>(&h);
}
__device__ __forceinline__ void mma_f16(float& d0, float& d1, float& d2, float& d3,
                                        uint32_t a0, uint32_t a1, uint32_t a2, uint32_t a3,
                                        uint32_t b0, uint32_t b1) {
    asm volatile("mma.sync.aligned.m16n8k16.row.col.f32.f16.f16.f32 "
                 "{%0,%1,%2,%3}, {%4,%5,%6,%7}, {%8,%9}, {%0,%1,%2,%3};"
                 : "+f"(d0), "+f"(d1), "+f"(d2), "+f"(d3)
                 : "r"(a0), "r"(a1), "r"(a2), "r"(a3), "r"(b0), "r"(b1));
}

__device__ __forceinline__ float gelu_exact(float x) {
    return 0.5f * x * (1.f + erff(x * 0.7071067811865475f));
}

// ---------------- fp16 mma.sync GEMM: C[M,N] = A[M,K] @ Bt[N,K]^T ---------
// Block 128x128, 8 warps (2x4), warp tile 64x32, BK=32 (2 x k16 chunks).
// Fragment-ordered smem, double-buffered: As[stage][kc][mt][reg4][lane32]
#define BM 128
#define BN 128
#define BK 32

__global__ void __launch_bounds__(256, 2)
gemm_tc(const float* __restrict__ A, const float* __restrict__ Bt,
        const float* __restrict__ bias, float* __restrict__ C,
        int M, int N, int K, int flags) {
    __shared__ uint32_t As[2][2][8][4][32];   // 16 KB total
    __shared__ uint32_t Bs[2][2][16][2][32];  // 16 KB total

    int tid = threadIdx.x;
    int wid = tid >> 5;
    int lane = tid & 31;
    int warp_row = wid >> 2;       // 0..1
    int warp_col = wid & 3;        // 0..3
    int row0 = blockIdx.y * BM, col0 = blockIdx.x * BN;

    const float* Ag = A + (size_t)row0 * K;
    const float* Bg = Bt + (size_t)col0 * K;

    float acc[4][4][4];
    #pragma unroll
    for (int i = 0; i < 4; ++i)
        #pragma unroll
        for (int j = 0; j < 4; ++j)
            #pragma unroll
            for (int q = 0; q < 4; ++q) acc[i][j][q] = 0.f;

    int nIter = K / BK;
    uint32_t pa[4][2], pb[4][2];

    // precomputed staging indices (same for every stage)
    int r_  = 0, c4_ = 0;  // per-j values recomputed inline

    // ---- load stage 0 into regs ----
    #pragma unroll
    for (int j = 0; j < 4; ++j) {
        int idx = tid + j * 256;
        int r = idx >> 3, c4 = idx & 7;
        float4 va = *reinterpret_cast<const float4*>(Ag + (size_t)r * K + c4 * 4);
        float4 vb = *reinterpret_cast<const float4*>(Bg + (size_t)r * K + c4 * 4);
        pa[j][0] = pack_h2(va.x, va.y); pa[j][1] = pack_h2(va.z, va.w);
        pb[j][0] = pack_h2(vb.x, vb.y); pb[j][1] = pack_h2(vb.z, vb.w);
    }
    // ---- store stage 0 ----
    #pragma unroll
    for (int j = 0; j < 4; ++j) {
        int idx = tid + j * 256;
        int r = idx >> 3, c4 = idx & 7;
        int kc = c4 >> 2;
        int km0 = (c4 & 3) * 4;
        int rega = ((km0 & 8) ? 2 : 0) | ((r & 8) ? 1 : 0);
        int lane0 = ((r & 7) << 2) | ((km0 & 4) >> 1);
        As[0][kc][r >> 4][rega][lane0]     = pa[j][0];
        As[0][kc][r >> 4][rega][lane0 + 1] = pa[j][1];
        int regb = (km0 & 8) ? 1 : 0;
        Bs[0][kc][r >> 3][regb][lane0]     = pb[j][0];
        Bs[0][kc][r >> 3][regb][lane0 + 1] = pb[j][1];
    }
    __syncthreads();

    for (int it = 0; it < nIter; ++it) {
        int s = it & 1;
        bool more = (it + 1 < nIter);
        if (more) {
            int kk = (it + 1) * BK;
            #pragma unroll
            for (int j = 0; j < 4; ++j) {
                int idx = tid + j * 256;
                int r = idx >> 3, c4 = idx & 7;
                float4 va = *reinterpret_cast<const float4*>(Ag + (size_t)r * K + kk + c4 * 4);
                float4 vb = *reinterpret_cast<const float4*>(Bg + (size_t)r * K + kk + c4 * 4);
                pa[j][0] = pack_h2(va.x, va.y); pa[j][1] = pack_h2(va.z, va.w);
                pb[j][0] = pack_h2(vb.x, vb.y); pb[j][1] = pack_h2(vb.z, vb.w);
            }
        }
        // compute on stage s
        #pragma unroll
        for (int kc = 0; kc < 2; ++kc) {
            uint32_t af[4][4], bf[4][2];
            #pragma unroll
            for (int mt = 0; mt < 4; ++mt) {
                int mtg = warp_row * 4 + mt;
                af[mt][0] = As[s][kc][mtg][0][lane];
                af[mt][1] = As[s][kc][mtg][1][lane];
                af[mt][2] = As[s][kc][mtg][2][lane];
                af[mt][3] = As[s][kc][mtg][3][lane];
            }
            #pragma unroll
            for (int nt = 0; nt < 4; ++nt) {
                int ntg = warp_col * 4 + nt;
                bf[nt][0] = Bs[s][kc][ntg][0][lane];
                bf[nt][1] = Bs[s][kc][ntg][1][lane];
            }
            #pragma unroll
            for (int mt = 0; mt < 4; ++mt)
                #pragma unroll
                for (int nt = 0; nt < 4; ++nt)
                    mma_f16(acc[mt][nt][0], acc[mt][nt][1], acc[mt][nt][2], acc[mt][nt][3],
                            af[mt][0], af[mt][1], af[mt][2], af[mt][3],
                            bf[nt][0], bf[nt][1]);
        }
        if (more) {
            int sn = s ^ 1;
            #pragma unroll
            for (int j = 0; j < 4; ++j) {
                int idx = tid + j * 256;
                int r = idx >> 3, c4 = idx & 7;
                int kc = c4 >> 2;
                int km0 = (c4 & 3) * 4;
                int rega = ((km0 & 8) ? 2 : 0) | ((r & 8) ? 1 : 0);
                int lane0 = ((r & 7) << 2) | ((km0 & 4) >> 1);
                As[sn][kc][r >> 4][rega][lane0]     = pa[j][0];
                As[sn][kc][r >> 4][rega][lane0 + 1] = pa[j][1];
                int regb = (km0 & 8) ? 1 : 0;
                Bs[sn][kc][r >> 3][regb][lane0]     = pb[j][0];
                Bs[sn][kc][r >> 3][regb][lane0 + 1] = pb[j][1];
            }
            __syncthreads();
        }
    }

    // epilogue (C layout of m16n8k16 == m16n8k8)
    int g = lane >> 2, tg = lane & 3;
    #pragma unroll
    for (int mt = 0; mt < 4; ++mt) {
        int rbase = row0 + warp_row * 64 + mt * 16 + g;
        #pragma unroll
        for (int nt = 0; nt < 4; ++nt) {
            int c = col0 + warp_col * 32 + nt * 8 + tg * 2;
            float2 bs = *reinterpret_cast<const float2*>(&bias[c]);
            float v0 = acc[mt][nt][0] + bs.x;
            float v1 = acc[mt][nt][1] + bs.y;
            float v2 = acc[mt][nt][2] + bs.x;
            float v3 = acc[mt][nt][3] + bs.y;
            if (flags & 2) { v0 = gelu_exact(v0); v1 = gelu_exact(v1); v2 = gelu_exact(v2); v3 = gelu_exact(v3); }
            float2* cp0 = reinterpret_cast<float2*>(C + (size_t)rbase * N + c);
            float2* cp1 = reinterpret_cast<float2*>(C + (size_t)(rbase + 8) * N + c);
            if (flags & 1) {
                float2 o0 = *cp0, o1 = *cp1;
                v0 += o0.x; v1 += o0.y; v2 += o1.x; v3 += o1.y;
            }
            float2 r0 = {v0, v1}, r1 = {v2, v3};
            *cp0 = r0;
            *cp1 = r1;
        }
    }
}

// ---------------- weight transpose ----------------
__global__ void transpose_kernel(const float* __restrict__ src, float* __restrict__ dst,
                                 int R, int C) {
    __shared__ float t[32][33];
    int bx = blockIdx.x * 32, by = blockIdx.y * 32;
    int x = bx + threadIdx.x;
    #pragma unroll
    for (int j = 0; j < 32; j += 8)
        t[threadIdx.y + j][threadIdx.x] = src[(size_t)(by + threadIdx.y + j) * C + x];
    __syncthreads();
    int xo = by + threadIdx.x;
    #pragma unroll
    for (int j = 0; j < 32; j += 8)
        dst[(size_t)(bx + threadIdx.y + j) * R + xo] = t[threadIdx.x][threadIdx.y + j];
}

// ---------------- CSR build ----------------
__global__ void deg_count_kernel(const int* __restrict__ ei) {
    int e = blockIdx.x * 256 + threadIdx.x;
    if (e < kE) atomicAdd(&g_deg[ei[kE + e]], 1);
}
__global__ void prefix_kernel() {
    __shared__ int sums[1024];
    int t = threadIdx.x;
    int base = t * 32;
    int s = 0;
    #pragma unroll 4
    for (int i = 0; i < 32; ++i) s += g_deg[base + i];
    sums[t] = s;
    __syncthreads();
    for (int o = 1; o < 1024; o <<= 1) {
        int v = (t >= o) ? sums[t - o] : 0;
        __syncthreads();
        sums[t] += v;
        __syncthreads();
    }
    int run = sums[t] - s;
    for (int i = 0; i < 32; ++i) { g_off[base + i] = run; run += g_deg[base + i]; }
    if (t == 1023) g_off[kN] = run;
}
__global__ void scatter_kernel(const int* __restrict__ ei) {
    int e = blockIdx.x * 256 + threadIdx.x;
    if (e < kE) {
        int d = ei[kE + e];
        int pos = g_off[d] + atomicAdd(&g_fill[d], 1);
        g_csr[pos] = ei[e];
    }
}

// ---------------- LayerNorm ----------------
__global__ void ln_kernel(const float* __restrict__ x, const float* __restrict__ g,
                          const float* __restrict__ b, float* __restrict__ y) {
    int t = threadIdx.x;
    int row = blockIdx.x;
    float v = x[(size_t)row * kD + t];
    __shared__ float sh[8];
    float s = v;
    #pragma unroll
    for (int o = 16; o; o >>= 1) s += __shfl_xor_sync(0xffffffffu, s, o);
    if ((t & 31) == 0) sh[t >> 5] = s;
    __syncthreads();
    float mean = (sh[0]+sh[1]+sh[2]+sh[3]+sh[4]+sh[5]+sh[6]+sh[7]) * (1.f / kD);
    float d = v - mean;
    float sq = d * d;
    __syncthreads();
    #pragma unroll
    for (int o = 16; o; o >>= 1) sq += __shfl_xor_sync(0xffffffffu, sq, o);
    if ((t & 31) == 0) sh[t >> 5] = sq;
    __syncthreads();
    float var = (sh[0]+sh[1]+sh[2]+sh[3]+sh[4]+sh[5]+sh[6]+sh[7]) * (1.f / kD);
    y[(size_t)row * kD + t] = d * rsqrtf(var + 1e-5f) * g[t] + b[t];
}

// ---------------- Edge attention (q,k,v packed stride 768) ----------------
__global__ void attn_kernel() {
    int gw = (blockIdx.x * blockDim.x + threadIdx.x) >> 5;
    int lane = threadIdx.x & 31;
    int node = gw >> 3;
    int head = gw & 7;
    if (node >= kN) return;
    int hd = head * kDH + lane;
    int beg = g_off[node], end = g_off[node + 1];
    if (beg == end) { g_agg[node * kTD + hd] = 0.f; return; }
    const float qv = g_qkv[node * kQKV + hd];
    float m = -INFINITY, l = 0.f, acc = 0.f;
    for (int i = beg - 1; i < end; ++i) {
        int src = (i < beg) ? node : g_csr[i];
        int sb = src * kQKV + hd;
        float s = qv * g_qkv[sb + 256];
        s += __shfl_xor_sync(0xffffffffu, s, 16);
        s += __shfl_xor_sync(0xffffffffu, s, 8);
        s += __shfl_xor_sync(0xffffffffu, s, 4);
        s += __shfl_xor_sync(0xffffffffu, s, 2);
        s += __shfl_xor_sync(0xffffffffu, s, 1);
        s *= 0.17677669529663687f;
        float mn = fmaxf(m, s);
        float corr = __expf(m - mn);
        float p = __expf(s - mn);
        l = l * corr + p;
        acc = acc * corr + p * g_qkv[sb + 512];
        m = mn;
    }
    g_agg[node * kTD + hd] = acc / l;
}

// ---------------- host orchestration ----------------
static inline void gemm(const float* A, const float* Bt, const float* bias, float* C,
                        int M, int N, int K, int flags) {
    dim3 g(N / BN, M / BM);
    gemm_tc<<<g, 256>>>(A, Bt, bias, C, M, N, K, flags);
}
static inline void transpose(const float* src, float* dst, int R, int C) {
    dim3 g(C / 32, R / 32), b(32, 8);
    transpose_kernel<<<g, b>>>(src, dst, R, C);
}

extern "C" void kernel_launch(void* const* d_in, const int* in_sizes, int n_in,
                              void* d_out, int out_size) {
    const float* x     = (const float*)d_in[0];
    const int*   ei    = (const int*)  d_in[1];
    const float* w_in  = (const float*)d_in[2];
    const float* b_in  = (const float*)d_in[3];
    const float* ln1_g = (const float*)d_in[4];
    const float* ln1_b = (const float*)d_in[5];
    const float* ln2_g = (const float*)d_in[6];
    const float* ln2_b = (const float*)d_in[7];
    const float* wq = (const float*)d_in[8];  const float* bq = (const float*)d_in[9];
    const float* wk = (const float*)d_in[10]; const float* bk = (const float*)d_in[11];
    const float* wv = (const float*)d_in[12]; const float* bv = (const float*)d_in[13];
    const float* wo = (const float*)d_in[14]; const float* bo = (const float*)d_in[15];
    const float* w1 = (const float*)d_in[16]; const float* b1 = (const float*)d_in[17];
    const float* w2 = (const float*)d_in[18]; const float* b2 = (const float*)d_in[19];
    float* h = (float*)d_out;

    float *xn, *qkv, *agg, *ffn, *wqkvT, *woT, *w1T, *w2T, *bqkv;
    int *deg, *fill;
    cudaGetSymbolAddress((void**)&xn,    g_xn);
    cudaGetSymbolAddress((void**)&qkv,   g_qkv);
    cudaGetSymbolAddress((void**)&agg,   g_agg);
    cudaGetSymbolAddress((void**)&ffn,   g_ffn);
    cudaGetSymbolAddress((void**)&wqkvT, g_wqkvT);
    cudaGetSymbolAddress((void**)&woT,   g_woT);
    cudaGetSymbolAddress((void**)&w1T,   g_w1T);
    cudaGetSymbolAddress((void**)&w2T,   g_w2T);
    cudaGetSymbolAddress((void**)&bqkv,  g_bqkv);
    cudaGetSymbolAddress((void**)&deg,   g_deg);
    cudaGetSymbolAddress((void**)&fill,  g_fill);

    // ---- CSR by dst ----
    cudaMemsetAsync(deg,  0, kN * sizeof(int));
    cudaMemsetAsync(fill, 0, kN * sizeof(int));
    deg_count_kernel<<<kE / 256, 256>>>(ei);
    prefix_kernel<<<1, 1024>>>();
    scatter_kernel<<<kE / 256, 256>>>(ei);

    // ---- weight transposes + bias packing ----
    transpose(w_in, xn, kD, kD);   // xn[0:65536] = w_inT (consumed before LN writes)
    for (int l = 0; l < kL; ++l) {
        transpose(wq + (size_t)l * kD * kTD, wqkvT + (size_t)l * kQKV * kD + 0 * kTD * kD, kD, kTD);
        transpose(wk + (size_t)l * kD * kTD, wqkvT + (size_t)l * kQKV * kD + 1 * kTD * kD, kD, kTD);
        transpose(wv + (size_t)l * kD * kTD, wqkvT + (size_t)l * kQKV * kD + 2 * kTD * kD, kD, kTD);
        transpose(wo + (size_t)l * kTD * kD, woT + (size_t)l * kD * kTD, kTD, kD);
        transpose(w1 + (size_t)l * kD * kFFN, w1T + (size_t)l * kFFN * kD, kD, kFFN);
        transpose(w2 + (size_t)l * kFFN * kD, w2T + (size_t)l * kD * kFFN, kFFN, kD);
        cudaMemcpyAsync(bqkv + (size_t)l * kQKV + 0,   bq + (size_t)l * kTD, kTD * 4, cudaMemcpyDeviceToDevice);
        cudaMemcpyAsync(bqkv + (size_t)l * kQKV + 256, bk + (size_t)l * kTD, kTD * 4, cudaMemcpyDeviceToDevice);
        cudaMemcpyAsync(bqkv + (size_t)l * kQKV + 512, bv + (size_t)l * kTD, kTD * 4, cudaMemcpyDeviceToDevice);
    }

    // ---- input projection: h = x @ w_in + b_in  (w_inT staged in xn) ----
    gemm(x, xn, b_in, h, kN, kD, kD, 0);

    for (int l = 0; l < kL; ++l) {
        ln_kernel<<<kN, 256>>>(h, ln1_g + l * kD, ln1_b + l * kD, xn);
        gemm(xn, wqkvT + (size_t)l * kQKV * kD, bqkv + (size_t)l * kQKV, qkv, kN, kQKV, kD, 0);
        attn_kernel<<<kN, 256>>>();
        gemm(agg, woT + (size_t)l * kD * kTD, bo + (size_t)l * kD, h, kN, kD, kTD, 1);
        ln_kernel<<<kN, 256>>>(h, ln2_g + l * kD, ln2_b + l * kD, xn);
        gemm(xn, w1T + (size_t)l * kFFN * kD, b1 + (size_t)l * kFFN, ffn, kN, kFFN, kD, 2);
        gemm(ffn, w2T + (size_t)l * kD * kFFN, b2 + (size_t)l * kD, h, kN, kD, kFFN, 1);
    }
}

// round 6
// speedup vs baseline: 2.6990x; 1.1037x over previous
#include <cuda_runtime.h>
#include <cuda_fp16.h>
#include <math.h>
#include <stdint.h>

#define kN   32768
#define kE   (kN * 16)
#define kD   256
#define kH   8
#define kDH  32
#define kTD  256
#define kFFN 1024
#define kL   2
#define kQKV 768

// ---------------- device scratch ----------------
__device__ float  g_xn  [kN * kD];
__device__ float  g_q   [kN * kTD];
__device__ __half g_kv  [kN * kTD * 2];   // interleaved (k,v) halves
__device__ float  g_agg [kN * kTD];
__device__ __half g_ffnh[kN * kFFN];
__device__ float  g_wqkvT[kL * kQKV * kD];
__device__ float  g_woT  [kL * kD * kTD];
__device__ float  g_w1T  [kL * kFFN * kD];
__device__ float  g_w2T  [kL * kD * kFFN];
__device__ float  g_bqkv [kL * kQKV];
__device__ int    g_deg [kN];
__device__ int    g_fill[kN];
__device__ int    g_off [kN + 1];
__device__ int    g_csr [kE];

// ---------------- fp16 helpers ----------------
__device__ __forceinline__ uint32_t pack_h2(float lo, float hi) {
    __half2 h = __floats2half2_rn(lo, hi);
    return *reinterpret_cast<uint32_t*>(&h);
}
__device__ __forceinline__ void mma_f16(float& d0, float& d1, float& d2, float& d3,
                                        uint32_t a0, uint32_t a1, uint32_t a2, uint32_t a3,
                                        uint32_t b0, uint32_t b1) {
    asm volatile("mma.sync.aligned.m16n8k16.row.col.f32.f16.f16.f32 "
                 "{%0,%1,%2,%3}, {%4,%5,%6,%7}, {%8,%9}, {%0,%1,%2,%3};"
                 : "+f"(d0), "+f"(d1), "+f"(d2), "+f"(d3)
                 : "r"(a0), "r"(a1), "r"(a2), "r"(a3), "r"(b0), "r"(b1));
}

__device__ __forceinline__ float gelu_exact(float x) {
    return 0.5f * x * (1.f + erff(x * 0.7071067811865475f));
}

// ---------------- fp16 mma.sync GEMM: C[M,N] = A[M,K] @ Bt[N,K]^T ---------
// Block 128x128, 8 warps (2x4), warp tile 64x32, BK=32.
// flags: 0 = plain fp32 out, 1 = residual fp32 out,
//        2 = gelu -> fp16 out (aux), 3 = qkv pack (q fp32 in C, k/v half2 in aux)
#define BM 128
#define BN 128
#define BK 32

template <int AFP16>
__global__ void __launch_bounds__(256, 2)
gemm_tc(const void* __restrict__ Av, const float* __restrict__ Bt,
        const float* __restrict__ bias, float* __restrict__ C,
        __half* __restrict__ aux,
        int M, int N, int K, int flags) {
    __shared__ uint32_t As[2][2][8][4][32];
    __shared__ uint32_t Bs[2][2][16][2][32];

    const float*  Af = (const float*)Av;
    const __half* Ah = (const __half*)Av;

    int tid = threadIdx.x;
    int lane = tid & 31;
    int wid = tid >> 5;
    int warp_row = wid >> 2;
    int warp_col = wid & 3;
    int row0 = blockIdx.y * BM, col0 = blockIdx.x * BN;

    const float*  Agf = Af + (size_t)row0 * K;
    const __half* Agh = Ah + (size_t)row0 * K;
    const float*  Bg  = Bt + (size_t)col0 * K;

    float acc[4][4][4];
    #pragma unroll
    for (int i = 0; i < 4; ++i)
        #pragma unroll
        for (int j = 0; j < 4; ++j)
            #pragma unroll
            for (int q = 0; q < 4; ++q) acc[i][j][q] = 0.f;

    int nIter = K / BK;
    uint32_t pa[4][2], pb[4][2];

    // ---- load stage 0 ----
    #pragma unroll
    for (int j = 0; j < 4; ++j) {
        int idx = tid + j * 256;
        int r = idx >> 3, c4 = idx & 7;
        if (AFP16) {
            uint2 u = *reinterpret_cast<const uint2*>(Agh + (size_t)r * K + c4 * 4);
            pa[j][0] = u.x; pa[j][1] = u.y;
        } else {
            float4 va = *reinterpret_cast<const float4*>(Agf + (size_t)r * K + c4 * 4);
            pa[j][0] = pack_h2(va.x, va.y); pa[j][1] = pack_h2(va.z, va.w);
        }
        float4 vb = *reinterpret_cast<const float4*>(Bg + (size_t)r * K + c4 * 4);
        pb[j][0] = pack_h2(vb.x, vb.y); pb[j][1] = pack_h2(vb.z, vb.w);
    }
    #pragma unroll
    for (int j = 0; j < 4; ++j) {
        int idx = tid + j * 256;
        int r = idx >> 3, c4 = idx & 7;
        int kc = c4 >> 2;
        int km0 = (c4 & 3) * 4;
        int rega = ((km0 & 8) ? 2 : 0) | ((r & 8) ? 1 : 0);
        int lane0 = ((r & 7) << 2) | ((km0 & 4) >> 1);
        As[0][kc][r >> 4][rega][lane0]     = pa[j][0];
        As[0][kc][r >> 4][rega][lane0 + 1] = pa[j][1];
        int regb = (km0 & 8) ? 1 : 0;
        Bs[0][kc][r >> 3][regb][lane0]     = pb[j][0];
        Bs[0][kc][r >> 3][regb][lane0 + 1] = pb[j][1];
    }
    __syncthreads();

    for (int it = 0; it < nIter; ++it) {
        int s = it & 1;
        bool more = (it + 1 < nIter);
        if (more) {
            int kk = (it + 1) * BK;
            #pragma unroll
            for (int j = 0; j < 4; ++j) {
                int idx = tid + j * 256;
                int r = idx >> 3, c4 = idx & 7;
                if (AFP16) {
                    uint2 u = *reinterpret_cast<const uint2*>(Agh + (size_t)r * K + kk + c4 * 4);
                    pa[j][0] = u.x; pa[j][1] = u.y;
                } else {
                    float4 va = *reinterpret_cast<const float4*>(Agf + (size_t)r * K + kk + c4 * 4);
                    pa[j][0] = pack_h2(va.x, va.y); pa[j][1] = pack_h2(va.z, va.w);
                }
                float4 vb = *reinterpret_cast<const float4*>(Bg + (size_t)r * K + kk + c4 * 4);
                pb[j][0] = pack_h2(vb.x, vb.y); pb[j][1] = pack_h2(vb.z, vb.w);
            }
        }
        #pragma unroll
        for (int kc = 0; kc < 2; ++kc) {
            uint32_t af[4][4], bf[4][2];
            #pragma unroll
            for (int mt = 0; mt < 4; ++mt) {
                int mtg = warp_row * 4 + mt;
                af[mt][0] = As[s][kc][mtg][0][lane];
                af[mt][1] = As[s][kc][mtg][1][lane];
                af[mt][2] = As[s][kc][mtg][2][lane];
                af[mt][3] = As[s][kc][mtg][3][lane];
            }
            #pragma unroll
            for (int nt = 0; nt < 4; ++nt) {
                int ntg = warp_col * 4 + nt;
                bf[nt][0] = Bs[s][kc][ntg][0][lane];
                bf[nt][1] = Bs[s][kc][ntg][1][lane];
            }
            #pragma unroll
            for (int mt = 0; mt < 4; ++mt)
                #pragma unroll
                for (int nt = 0; nt < 4; ++nt)
                    mma_f16(acc[mt][nt][0], acc[mt][nt][1], acc[mt][nt][2], acc[mt][nt][3],
                            af[mt][0], af[mt][1], af[mt][2], af[mt][3],
                            bf[nt][0], bf[nt][1]);
        }
        if (more) {
            int sn = s ^ 1;
            #pragma unroll
            for (int j = 0; j < 4; ++j) {
                int idx = tid + j * 256;
                int r = idx >> 3, c4 = idx & 7;
                int kc = c4 >> 2;
                int km0 = (c4 & 3) * 4;
                int rega = ((km0 & 8) ? 2 : 0) | ((r & 8) ? 1 : 0);
                int lane0 = ((r & 7) << 2) | ((km0 & 4) >> 1);
                As[sn][kc][r >> 4][rega][lane0]     = pa[j][0];
                As[sn][kc][r >> 4][rega][lane0 + 1] = pa[j][1];
                int regb = (km0 & 8) ? 1 : 0;
                Bs[sn][kc][r >> 3][regb][lane0]     = pb[j][0];
                Bs[sn][kc][r >> 3][regb][lane0 + 1] = pb[j][1];
            }
            __syncthreads();
        }
    }

    // ---- epilogue ----
    int g = lane >> 2, tg = lane & 3;
    bool isq = (col0 < 256);
    bool isv = (col0 >= 512);
    #pragma unroll
    for (int mt = 0; mt < 4; ++mt) {
        int rbase = row0 + warp_row * 64 + mt * 16 + g;
        #pragma unroll
        for (int nt = 0; nt < 4; ++nt) {
            int c = col0 + warp_col * 32 + nt * 8 + tg * 2;
            float2 bs = *reinterpret_cast<const float2*>(&bias[c]);
            float v0 = acc[mt][nt][0] + bs.x;
            float v1 = acc[mt][nt][1] + bs.y;
            float v2 = acc[mt][nt][2] + bs.x;
            float v3 = acc[mt][nt][3] + bs.y;
            if (flags == 2) {
                v0 = gelu_exact(v0); v1 = gelu_exact(v1);
                v2 = gelu_exact(v2); v3 = gelu_exact(v3);
                __half2* o0 = reinterpret_cast<__half2*>(aux + (size_t)rbase * N + c);
                __half2* o1 = reinterpret_cast<__half2*>(aux + (size_t)(rbase + 8) * N + c);
                *o0 = __floats2half2_rn(v0, v1);
                *o1 = __floats2half2_rn(v2, v3);
            } else if (flags == 3) {
                if (isq) {
                    float2 w0 = {v0, v1}, w1 = {v2, v3};
                    *reinterpret_cast<float2*>(C + (size_t)rbase * kTD + c) = w0;
                    *reinterpret_cast<float2*>(C + (size_t)(rbase + 8) * kTD + c) = w1;
                } else {
                    int sel = isv ? 1 : 0;
                    int cm = c - (isv ? 512 : 256);
                    aux[((size_t)rbase * kTD + cm) * 2 + sel]       = __float2half_rn(v0);
                    aux[((size_t)rbase * kTD + cm + 1) * 2 + sel]   = __float2half_rn(v1);
                    aux[((size_t)(rbase + 8) * kTD + cm) * 2 + sel] = __float2half_rn(v2);
                    aux[((size_t)(rbase + 8) * kTD + cm + 1) * 2 + sel] = __float2half_rn(v3);
                }
            } else {
                float2* cp0 = reinterpret_cast<float2*>(C + (size_t)rbase * N + c);
                float2* cp1 = reinterpret_cast<float2*>(C + (size_t)(rbase + 8) * N + c);
                if (flags == 1) {
                    float2 o0 = *cp0, o1 = *cp1;
                    v0 += o0.x; v1 += o0.y; v2 += o1.x; v3 += o1.y;
                }
                float2 r0 = {v0, v1}, r1 = {v2, v3};
                *cp0 = r0;
                *cp1 = r1;
            }
        }
    }
}

// ---------------- weight transpose ----------------
__global__ void transpose_kernel(const float* __restrict__ src, float* __restrict__ dst,
                                 int R, int C) {
    __shared__ float t[32][33];
    int bx = blockIdx.x * 32, by = blockIdx.y * 32;
    int x = bx + threadIdx.x;
    #pragma unroll
    for (int j = 0; j < 32; j += 8)
        t[threadIdx.y + j][threadIdx.x] = src[(size_t)(by + threadIdx.y + j) * C + x];
    __syncthreads();
    int xo = by + threadIdx.x;
    #pragma unroll
    for (int j = 0; j < 32; j += 8)
        dst[(size_t)(bx + threadIdx.y + j) * R + xo] = t[threadIdx.x][threadIdx.y + j];
}

// ---------------- CSR build ----------------
__global__ void deg_count_kernel(const int* __restrict__ ei) {
    int e = blockIdx.x * 256 + threadIdx.x;
    if (e < kE) atomicAdd(&g_deg[ei[kE + e]], 1);
}
__global__ void prefix_kernel() {
    __shared__ int sums[1024];
    int t = threadIdx.x;
    int base = t * 32;
    int s = 0;
    #pragma unroll 4
    for (int i = 0; i < 32; ++i) s += g_deg[base + i];
    sums[t] = s;
    __syncthreads();
    for (int o = 1; o < 1024; o <<= 1) {
        int v = (t >= o) ? sums[t - o] : 0;
        __syncthreads();
        sums[t] += v;
        __syncthreads();
    }
    int run = sums[t] - s;
    for (int i = 0; i < 32; ++i) { g_off[base + i] = run; run += g_deg[base + i]; }
    if (t == 1023) g_off[kN] = run;
}
__global__ void scatter_kernel(const int* __restrict__ ei) {
    int e = blockIdx.x * 256 + threadIdx.x;
    if (e < kE) {
        int d = ei[kE + e];
        int pos = g_off[d] + atomicAdd(&g_fill[d], 1);
        g_csr[pos] = ei[e];
    }
}

// ---------------- LayerNorm ----------------
__global__ void ln_kernel(const float* __restrict__ x, const float* __restrict__ g,
                          const float* __restrict__ b, float* __restrict__ y) {
    int t = threadIdx.x;
    int row = blockIdx.x;
    float v = x[(size_t)row * kD + t];
    __shared__ float sh[8];
    float s = v;
    #pragma unroll
    for (int o = 16; o; o >>= 1) s += __shfl_xor_sync(0xffffffffu, s, o);
    if ((t & 31) == 0) sh[t >> 5] = s;
    __syncthreads();
    float mean = (sh[0]+sh[1]+sh[2]+sh[3]+sh[4]+sh[5]+sh[6]+sh[7]) * (1.f / kD);
    float d = v - mean;
    float sq = d * d;
    __syncthreads();
    #pragma unroll
    for (int o = 16; o; o >>= 1) sq += __shfl_xor_sync(0xffffffffu, sq, o);
    if ((t & 31) == 0) sh[t >> 5] = sq;
    __syncthreads();
    float var = (sh[0]+sh[1]+sh[2]+sh[3]+sh[4]+sh[5]+sh[6]+sh[7]) * (1.f / kD);
    y[(size_t)row * kD + t] = d * rsqrtf(var + 1e-5f) * g[t] + b[t];
}

// ---------------- Edge attention: warp per (node, head), packed fp16 kv ----
__global__ void attn_kernel() {
    int lane = threadIdx.x & 31;
    int head = threadIdx.x >> 5;
    int node = blockIdx.x;
    int hd = head * kDH + lane;
    int beg = g_off[node], end = g_off[node + 1];
    if (beg == end) { g_agg[node * kTD + hd] = 0.f; return; }
    const float qv = g_q[node * kTD + hd] * 0.17677669529663687f;  // scale folded
    const uint32_t* kvp = reinterpret_cast<const uint32_t*>(g_kv);
    float l = 0.f, acc = 0.f;

    // self edge (scores are tiny; no max-shift needed, softmax is shift-invariant)
    {
        uint32_t u = kvp[(size_t)node * kTD + hd];
        float2 f = __half22float2(*reinterpret_cast<const __half2*>(&u));
        float s = qv * f.x;
        s += __shfl_xor_sync(~0u, s, 16);
        s += __shfl_xor_sync(~0u, s, 8);
        s += __shfl_xor_sync(~0u, s, 4);
        s += __shfl_xor_sync(~0u, s, 2);
        s += __shfl_xor_sync(~0u, s, 1);
        float p = __expf(s);
        l += p; acc += p * f.y;
    }
    int i = beg;
    for (; i + 1 < end; i += 2) {
        int s0 = g_csr[i], s1 = g_csr[i + 1];
        uint32_t u0 = kvp[(size_t)s0 * kTD + hd];
        uint32_t u1 = kvp[(size_t)s1 * kTD + hd];
        float2 f0 = __half22float2(*reinterpret_cast<const __half2*>(&u0));
        float2 f1 = __half22float2(*reinterpret_cast<const __half2*>(&u1));
        float a = qv * f0.x, b = qv * f1.x;
        a += __shfl_xor_sync(~0u, a, 16); b += __shfl_xor_sync(~0u, b, 16);
        a += __shfl_xor_sync(~0u, a, 8);  b += __shfl_xor_sync(~0u, b, 8);
        a += __shfl_xor_sync(~0u, a, 4);  b += __shfl_xor_sync(~0u, b, 4);
        a += __shfl_xor_sync(~0u, a, 2);  b += __shfl_xor_sync(~0u, b, 2);
        a += __shfl_xor_sync(~0u, a, 1);  b += __shfl_xor_sync(~0u, b, 1);
        float p0 = __expf(a), p1 = __expf(b);
        l += p0 + p1;
        acc += p0 * f0.y + p1 * f1.y;
    }
    if (i < end) {
        int s0 = g_csr[i];
        uint32_t u = kvp[(size_t)s0 * kTD + hd];
        float2 f = __half22float2(*reinterpret_cast<const __half2*>(&u));
        float s = qv * f.x;
        s += __shfl_xor_sync(~0u, s, 16);
        s += __shfl_xor_sync(~0u, s, 8);
        s += __shfl_xor_sync(~0u, s, 4);
        s += __shfl_xor_sync(~0u, s, 2);
        s += __shfl_xor_sync(~0u, s, 1);
        float p = __expf(s);
        l += p; acc += p * f.y;
    }
    g_agg[node * kTD + hd] = acc / l;
}

// ---------------- host orchestration ----------------
static inline void gemm_f32(const float* A, const float* Bt, const float* bias,
                            float* C, __half* aux, int M, int N, int K, int flags) {
    dim3 g(N / BN, M / BM);
    gemm_tc<0><<<g, 256>>>(A, Bt, bias, C, aux, M, N, K, flags);
}
static inline void gemm_f16(const __half* A, const float* Bt, const float* bias,
                            float* C, __half* aux, int M, int N, int K, int flags) {
    dim3 g(N / BN, M / BM);
    gemm_tc<1><<<g, 256>>>(A, Bt, bias, C, aux, M, N, K, flags);
}
static inline void transpose(const float* src, float* dst, int R, int C) {
    dim3 g(C / 32, R / 32), b(32, 8);
    transpose_kernel<<<g, b>>>(src, dst, R, C);
}

extern "C" void kernel_launch(void* const* d_in, const int* in_sizes, int n_in,
                              void* d_out, int out_size) {
    const float* x     = (const float*)d_in[0];
    const int*   ei    = (const int*)  d_in[1];
    const float* w_in  = (const float*)d_in[2];
    const float* b_in  = (const float*)d_in[3];
    const float* ln1_g = (const float*)d_in[4];
    const float* ln1_b = (const float*)d_in[5];
    const float* ln2_g = (const float*)d_in[6];
    const float* ln2_b = (const float*)d_in[7];
    const float* wq = (const float*)d_in[8];  const float* bq = (const float*)d_in[9];
    const float* wk = (const float*)d_in[10]; const float* bk = (const float*)d_in[11];
    const float* wv = (const float*)d_in[12]; const float* bv = (const float*)d_in[13];
    const float* wo = (const float*)d_in[14]; const float* bo = (const float*)d_in[15];
    const float* w1 = (const float*)d_in[16]; const float* b1 = (const float*)d_in[17];
    const float* w2 = (const float*)d_in[18]; const float* b2 = (const float*)d_in[19];
    float* h = (float*)d_out;

    float *xn, *q, *agg, *wqkvT, *woT, *w1T, *w2T, *bqkv;
    __half *kv, *ffnh;
    int *deg, *fill;
    cudaGetSymbolAddress((void**)&xn,    g_xn);
    cudaGetSymbolAddress((void**)&q,     g_q);
    cudaGetSymbolAddress((void**)&kv,    g_kv);
    cudaGetSymbolAddress((void**)&agg,   g_agg);
    cudaGetSymbolAddress((void**)&ffnh,  g_ffnh);
    cudaGetSymbolAddress((void**)&wqkvT, g_wqkvT);
    cudaGetSymbolAddress((void**)&woT,   g_woT);
    cudaGetSymbolAddress((void**)&w1T,   g_w1T);
    cudaGetSymbolAddress((void**)&w2T,   g_w2T);
    cudaGetSymbolAddress((void**)&bqkv,  g_bqkv);
    cudaGetSymbolAddress((void**)&deg,   g_deg);
    cudaGetSymbolAddress((void**)&fill,  g_fill);

    // ---- CSR by dst ----
    cudaMemsetAsync(deg,  0, kN * sizeof(int));
    cudaMemsetAsync(fill, 0, kN * sizeof(int));
    deg_count_kernel<<<kE / 256, 256>>>(ei);
    prefix_kernel<<<1, 1024>>>();
    scatter_kernel<<<kE / 256, 256>>>(ei);

    // ---- weight transposes + bias packing ----
    transpose(w_in, xn, kD, kD);   // xn[0:65536] = w_inT (consumed before LN writes)
    for (int l = 0; l < kL; ++l) {
        transpose(wq + (size_t)l * kD * kTD, wqkvT + (size_t)l * kQKV * kD + 0 * kTD * kD, kD, kTD);
        transpose(wk + (size_t)l * kD * kTD, wqkvT + (size_t)l * kQKV * kD + 1 * kTD * kD, kD, kTD);
        transpose(wv + (size_t)l * kD * kTD, wqkvT + (size_t)l * kQKV * kD + 2 * kTD * kD, kD, kTD);
        transpose(wo + (size_t)l * kTD * kD, woT + (size_t)l * kD * kTD, kTD, kD);
        transpose(w1 + (size_t)l * kD * kFFN, w1T + (size_t)l * kFFN * kD, kD, kFFN);
        transpose(w2 + (size_t)l * kFFN * kD, w2T + (size_t)l * kD * kFFN, kFFN, kD);
        cudaMemcpyAsync(bqkv + (size_t)l * kQKV + 0,   bq + (size_t)l * kTD, kTD * 4, cudaMemcpyDeviceToDevice);
        cudaMemcpyAsync(bqkv + (size_t)l * kQKV + 256, bk + (size_t)l * kTD, kTD * 4, cudaMemcpyDeviceToDevice);
        cudaMemcpyAsync(bqkv + (size_t)l * kQKV + 512, bv + (size_t)l * kTD, kTD * 4, cudaMemcpyDeviceToDevice);
    }

    // ---- input projection ----
    gemm_f32(x, xn, b_in, h, nullptr, kN, kD, kD, 0);

    for (int l = 0; l < kL; ++l) {
        ln_kernel<<<kN, 256>>>(h, ln1_g + l * kD, ln1_b + l * kD, xn);
        gemm_f32(xn, wqkvT + (size_t)l * kQKV * kD, bqkv + (size_t)l * kQKV,
                 q, kv, kN, kQKV, kD, 3);                                   // q fp32 + kv fp16 packed
        attn_kernel<<<kN, 256>>>();
        gemm_f32(agg, woT + (size_t)l * kD * kTD, bo + (size_t)l * kD,
                 h, nullptr, kN, kD, kTD, 1);                                // h += agg@wo + bo
        ln_kernel<<<kN, 256>>>(h, ln2_g + l * kD, ln2_b + l * kD, xn);
        gemm_f32(xn, w1T + (size_t)l * kFFN * kD, b1 + (size_t)l * kFFN,
                 nullptr, ffnh, kN, kFFN, kD, 2);                            // gelu -> fp16
        gemm_f16(ffnh, w2T + (size_t)l * kD * kFFN, b2 + (size_t)l * kD,
                 h, nullptr, kN, kD, kFFN, 1);                               // h += ffn@w2 + b2
    }
}

// round 7
// speedup vs baseline: 2.8720x; 1.0641x over previous
#include <cuda_runtime.h>
#include <cuda_fp16.h>
#include <math.h>
#include <stdint.h>

#define kN   32768
#define kE   (kN * 16)
#define kD   256
#define kH   8
#define kDH  32
#define kTD  256
#define kFFN 1024
#define kL   2
#define kQKV 768

// ---------------- device scratch ----------------
__device__ __half g_xh  [kN * kD];        // x in fp16
__device__ __half g_xnh [kN * kD];        // LN output fp16
__device__ float  g_q   [kN * kTD];
__device__ __half g_kv  [kN * kTD * 2];   // interleaved (k,v)
__device__ __half g_aggh[kN * kTD];
__device__ __half g_ffnh[kN * kFFN];
__device__ __half g_winT [kD * kD];
__device__ __half g_wqkvT[kL * kQKV * kD];
__device__ __half g_woT  [kL * kD * kTD];
__device__ __half g_w1T  [kL * kFFN * kD];
__device__ __half g_w2T  [kL * kD * kFFN];
__device__ float  g_bqkv [kL * kQKV];
__device__ int    g_deg [kN];
__device__ int    g_fill[kN];
__device__ int    g_off [kN + 1];
__device__ int    g_csr [kE];

// ---------------- helpers ----------------
__device__ __forceinline__ void mma_f16(float& d0, float& d1, float& d2, float& d3,
                                        uint32_t a0, uint32_t a1, uint32_t a2, uint32_t a3,
                                        uint32_t b0, uint32_t b1) {
    asm volatile("mma.sync.aligned.m16n8k16.row.col.f32.f16.f16.f32 "
                 "{%0,%1,%2,%3}, {%4,%5,%6,%7}, {%8,%9}, {%0,%1,%2,%3};"
                 : "+f"(d0), "+f"(d1), "+f"(d2), "+f"(d3)
                 : "r"(a0), "r"(a1), "r"(a2), "r"(a3), "r"(b0), "r"(b1));
}
__device__ __forceinline__ float gelu_exact(float x) {
    return 0.5f * x * (1.f + erff(x * 0.7071067811865475f));
}

// ---------------- fp16 mma.sync GEMM: C[M,N] = A[M,K] @ Bt[N,K]^T ---------
// flags: 0 plain fp32 out, 1 residual fp32 out, 2 gelu->fp16 aux,
//        3 qkv pack (q fp32 in C, k/v interleaved half in aux)
#define BM 128
#define BN 128
#define BK 32

__global__ void __launch_bounds__(256, 2)
gemm_tc(const __half* __restrict__ A, const __half* __restrict__ Bt,
        const float* __restrict__ bias, float* __restrict__ C,
        __half* __restrict__ aux,
        int M, int N, int K, int flags) {
    __shared__ uint32_t As[2][2][8][4][32];
    __shared__ uint32_t Bs[2][2][16][2][32];

    int tid = threadIdx.x;
    int lane = tid & 31;
    int wid = tid >> 5;
    int warp_row = wid >> 2;
    int warp_col = wid & 3;
    int row0 = blockIdx.y * BM, col0 = blockIdx.x * BN;

    const __half* Ag = A + (size_t)row0 * K;
    const __half* Bg = Bt + (size_t)col0 * K;

    float acc[4][4][4];
    #pragma unroll
    for (int i = 0; i < 4; ++i)
        #pragma unroll
        for (int j = 0; j < 4; ++j)
            #pragma unroll
            for (int q = 0; q < 4; ++q) acc[i][j][q] = 0.f;

    int nIter = K / BK;
    uint32_t pa[4][2], pb[4][2];

    #pragma unroll
    for (int j = 0; j < 4; ++j) {
        int idx = tid + j * 256;
        int r = idx >> 3, c4 = idx & 7;
        uint2 ua = *reinterpret_cast<const uint2*>(Ag + (size_t)r * K + c4 * 4);
        uint2 ub = *reinterpret_cast<const uint2*>(Bg + (size_t)r * K + c4 * 4);
        pa[j][0] = ua.x; pa[j][1] = ua.y;
        pb[j][0] = ub.x; pb[j][1] = ub.y;
    }
    #pragma unroll
    for (int j = 0; j < 4; ++j) {
        int idx = tid + j * 256;
        int r = idx >> 3, c4 = idx & 7;
        int kc = c4 >> 2;
        int km0 = (c4 & 3) * 4;
        int rega = ((km0 & 8) ? 2 : 0) | ((r & 8) ? 1 : 0);
        int lane0 = ((r & 7) << 2) | ((km0 & 4) >> 1);
        As[0][kc][r >> 4][rega][lane0]     = pa[j][0];
        As[0][kc][r >> 4][rega][lane0 + 1] = pa[j][1];
        int regb = (km0 & 8) ? 1 : 0;
        Bs[0][kc][r >> 3][regb][lane0]     = pb[j][0];
        Bs[0][kc][r >> 3][regb][lane0 + 1] = pb[j][1];
    }
    __syncthreads();

    for (int it = 0; it < nIter; ++it) {
        int s = it & 1;
        bool more = (it + 1 < nIter);
        if (more) {
            int kk = (it + 1) * BK;
            #pragma unroll
            for (int j = 0; j < 4; ++j) {
                int idx = tid + j * 256;
                int r = idx >> 3, c4 = idx & 7;
                uint2 ua = *reinterpret_cast<const uint2*>(Ag + (size_t)r * K + kk + c4 * 4);
                uint2 ub = *reinterpret_cast<const uint2*>(Bg + (size_t)r * K + kk + c4 * 4);
                pa[j][0] = ua.x; pa[j][1] = ua.y;
                pb[j][0] = ub.x; pb[j][1] = ub.y;
            }
        }
        #pragma unroll
        for (int kc = 0; kc < 2; ++kc) {
            uint32_t af[4][4], bf[4][2];
            #pragma unroll
            for (int mt = 0; mt < 4; ++mt) {
                int mtg = warp_row * 4 + mt;
                af[mt][0] = As[s][kc][mtg][0][lane];
                af[mt][1] = As[s][kc][mtg][1][lane];
                af[mt][2] = As[s][kc][mtg][2][lane];
                af[mt][3] = As[s][kc][mtg][3][lane];
            }
            #pragma unroll
            for (int nt = 0; nt < 4; ++nt) {
                int ntg = warp_col * 4 + nt;
                bf[nt][0] = Bs[s][kc][ntg][0][lane];
                bf[nt][1] = Bs[s][kc][ntg][1][lane];
            }
            #pragma unroll
            for (int mt = 0; mt < 4; ++mt)
                #pragma unroll
                for (int nt = 0; nt < 4; ++nt)
                    mma_f16(acc[mt][nt][0], acc[mt][nt][1], acc[mt][nt][2], acc[mt][nt][3],
                            af[mt][0], af[mt][1], af[mt][2], af[mt][3],
                            bf[nt][0], bf[nt][1]);
        }
        if (more) {
            int sn = s ^ 1;
            #pragma unroll
            for (int j = 0; j < 4; ++j) {
                int idx = tid + j * 256;
                int r = idx >> 3, c4 = idx & 7;
                int kc = c4 >> 2;
                int km0 = (c4 & 3) * 4;
                int rega = ((km0 & 8) ? 2 : 0) | ((r & 8) ? 1 : 0);
                int lane0 = ((r & 7) << 2) | ((km0 & 4) >> 1);
                As[sn][kc][r >> 4][rega][lane0]     = pa[j][0];
                As[sn][kc][r >> 4][rega][lane0 + 1] = pa[j][1];
                int regb = (km0 & 8) ? 1 : 0;
                Bs[sn][kc][r >> 3][regb][lane0]     = pb[j][0];
                Bs[sn][kc][r >> 3][regb][lane0 + 1] = pb[j][1];
            }
            __syncthreads();
        }
    }

    // ---- epilogue ----
    int g = lane >> 2, tg = lane & 3;
    bool isq = (col0 < 256);
    bool isv = (col0 >= 512);
    #pragma unroll
    for (int mt = 0; mt < 4; ++mt) {
        int rbase = row0 + warp_row * 64 + mt * 16 + g;
        #pragma unroll
        for (int nt = 0; nt < 4; ++nt) {
            int c = col0 + warp_col * 32 + nt * 8 + tg * 2;
            float2 bs = *reinterpret_cast<const float2*>(&bias[c]);
            float v0 = acc[mt][nt][0] + bs.x;
            float v1 = acc[mt][nt][1] + bs.y;
            float v2 = acc[mt][nt][2] + bs.x;
            float v3 = acc[mt][nt][3] + bs.y;
            if (flags == 2) {
                v0 = gelu_exact(v0); v1 = gelu_exact(v1);
                v2 = gelu_exact(v2); v3 = gelu_exact(v3);
                *reinterpret_cast<__half2*>(aux + (size_t)rbase * N + c)       = __floats2half2_rn(v0, v1);
                *reinterpret_cast<__half2*>(aux + (size_t)(rbase + 8) * N + c) = __floats2half2_rn(v2, v3);
            } else if (flags == 3) {
                if (isq) {
                    float2 w0 = {v0, v1}, w1 = {v2, v3};
                    *reinterpret_cast<float2*>(C + (size_t)rbase * kTD + c) = w0;
                    *reinterpret_cast<float2*>(C + (size_t)(rbase + 8) * kTD + c) = w1;
                } else {
                    int sel = isv ? 1 : 0;
                    int cm = c - (isv ? 512 : 256);
                    aux[((size_t)rbase * kTD + cm) * 2 + sel]           = __float2half_rn(v0);
                    aux[((size_t)rbase * kTD + cm + 1) * 2 + sel]       = __float2half_rn(v1);
                    aux[((size_t)(rbase + 8) * kTD + cm) * 2 + sel]     = __float2half_rn(v2);
                    aux[((size_t)(rbase + 8) * kTD + cm + 1) * 2 + sel] = __float2half_rn(v3);
                }
            } else {
                float2* cp0 = reinterpret_cast<float2*>(C + (size_t)rbase * N + c);
                float2* cp1 = reinterpret_cast<float2*>(C + (size_t)(rbase + 8) * N + c);
                if (flags == 1) {
                    float2 o0 = *cp0, o1 = *cp1;
                    v0 += o0.x; v1 += o0.y; v2 += o1.x; v3 += o1.y;
                }
                float2 r0 = {v0, v1}, r1 = {v2, v3};
                *cp0 = r0;
                *cp1 = r1;
            }
        }
    }
}

// ---------------- transpose + fp32->fp16: dst[C][R] = half(src[R][C]^T) ----
__global__ void transpose_h(const float* __restrict__ src, __half* __restrict__ dst,
                            int R, int C) {
    __shared__ float t[32][33];
    int bx = blockIdx.x * 32, by = blockIdx.y * 32;
    int x = bx + threadIdx.x;
    #pragma unroll
    for (int j = 0; j < 32; j += 8)
        t[threadIdx.y + j][threadIdx.x] = src[(size_t)(by + threadIdx.y + j) * C + x];
    __syncthreads();
    int xo = by + threadIdx.x;
    #pragma unroll
    for (int j = 0; j < 32; j += 8)
        dst[(size_t)(bx + threadIdx.y + j) * R + xo] = __float2half_rn(t[threadIdx.x][threadIdx.y + j]);
}
// fused 3-source transpose (QKV), z picks source; dst segment z*C*R
__global__ void transpose3_h(const float* s0, const float* s1, const float* s2,
                             __half* __restrict__ dst, int R, int C) {
    __shared__ float t[32][33];
    const float* src = (blockIdx.z == 0) ? s0 : (blockIdx.z == 1) ? s1 : s2;
    __half* d = dst + (size_t)blockIdx.z * C * R;
    int bx = blockIdx.x * 32, by = blockIdx.y * 32;
    int x = bx + threadIdx.x;
    #pragma unroll
    for (int j = 0; j < 32; j += 8)
        t[threadIdx.y + j][threadIdx.x] = src[(size_t)(by + threadIdx.y + j) * C + x];
    __syncthreads();
    int xo = by + threadIdx.x;
    #pragma unroll
    for (int j = 0; j < 32; j += 8)
        d[(size_t)(bx + threadIdx.y + j) * R + xo] = __float2half_rn(t[threadIdx.x][threadIdx.y + j]);
}

// ---------------- x -> fp16 ----------------
__global__ void cvt_x(const float* __restrict__ x, __half* __restrict__ xh) {
    int i = blockIdx.x * 256 + threadIdx.x;
    float4 v = reinterpret_cast<const float4*>(x)[i];
    __half2 h0 = __floats2half2_rn(v.x, v.y);
    __half2 h1 = __floats2half2_rn(v.z, v.w);
    uint2 u = {*reinterpret_cast<uint32_t*>(&h0), *reinterpret_cast<uint32_t*>(&h1)};
    reinterpret_cast<uint2*>(xh)[i] = u;
}

// ---------------- bias pack (bq|bk|bv per layer) ----------------
__global__ void pack_bias(const float* bq, const float* bk, const float* bv) {
    int t = blockIdx.x * 256 + threadIdx.x;     // 0..1535
    int l = t / kQKV, r = t % kQKV;
    const float* s = (r < 256) ? bq + l * kTD + r
                   : (r < 512) ? bk + l * kTD + (r - 256)
                               : bv + l * kTD + (r - 512);
    g_bqkv[t] = *s;
}

// ---------------- CSR build ----------------
__global__ void deg_count_kernel(const int* __restrict__ ei) {
    int e = blockIdx.x * 256 + threadIdx.x;
    if (e < kE) atomicAdd(&g_deg[ei[kE + e]], 1);
}
__global__ void prefix_kernel() {
    __shared__ int sums[1024];
    int t = threadIdx.x;
    int base = t * 32;
    int s = 0;
    #pragma unroll 4
    for (int i = 0; i < 32; ++i) s += g_deg[base + i];
    sums[t] = s;
    __syncthreads();
    for (int o = 1; o < 1024; o <<= 1) {
        int v = (t >= o) ? sums[t - o] : 0;
        __syncthreads();
        sums[t] += v;
        __syncthreads();
    }
    int run = sums[t] - s;
    for (int i = 0; i < 32; ++i) { g_off[base + i] = run; run += g_deg[base + i]; }
    if (t == 1023) g_off[kN] = run;
}
__global__ void scatter_kernel(const int* __restrict__ ei) {
    int e = blockIdx.x * 256 + threadIdx.x;
    if (e < kE) {
        int d = ei[kE + e];
        int pos = g_off[d] + atomicAdd(&g_fill[d], 1);
        g_csr[pos] = ei[e];
    }
}

// ---------------- LayerNorm (fp32 in, fp16 out) ----------------
__global__ void ln_kernel(const float* __restrict__ x, const float* __restrict__ g,
                          const float* __restrict__ b, __half* __restrict__ y) {
    int t = threadIdx.x;
    int row = blockIdx.x;
    float v = x[(size_t)row * kD + t];
    __shared__ float sh[8];
    float s = v;
    #pragma unroll
    for (int o = 16; o; o >>= 1) s += __shfl_xor_sync(0xffffffffu, s, o);
    if ((t & 31) == 0) sh[t >> 5] = s;
    __syncthreads();
    float mean = (sh[0]+sh[1]+sh[2]+sh[3]+sh[4]+sh[5]+sh[6]+sh[7]) * (1.f / kD);
    float d = v - mean;
    float sq = d * d;
    __syncthreads();
    #pragma unroll
    for (int o = 16; o; o >>= 1) sq += __shfl_xor_sync(0xffffffffu, sq, o);
    if ((t & 31) == 0) sh[t >> 5] = sq;
    __syncthreads();
    float var = (sh[0]+sh[1]+sh[2]+sh[3]+sh[4]+sh[5]+sh[6]+sh[7]) * (1.f / kD);
    y[(size_t)row * kD + t] = __float2half_rn(d * rsqrtf(var + 1e-5f) * g[t] + b[t]);
}

// ---------------- Edge attention ----------------
__global__ void attn_kernel() {
    int lane = threadIdx.x & 31;
    int head = threadIdx.x >> 5;
    int node = blockIdx.x;
    int hd = head * kDH + lane;
    int beg = g_off[node], end = g_off[node + 1];
    if (beg == end) { g_aggh[node * kTD + hd] = __float2half_rn(0.f); return; }
    const float qv = g_q[node * kTD + hd] * 0.17677669529663687f;
    const uint32_t* kvp = reinterpret_cast<const uint32_t*>(g_kv);
    float l = 0.f, acc = 0.f;
    {
        uint32_t u = kvp[(size_t)node * kTD + hd];
        float2 f = __half22float2(*reinterpret_cast<const __half2*>(&u));
        float s = qv * f.x;
        s += __shfl_xor_sync(~0u, s, 16);
        s += __shfl_xor_sync(~0u, s, 8);
        s += __shfl_xor_sync(~0u, s, 4);
        s += __shfl_xor_sync(~0u, s, 2);
        s += __shfl_xor_sync(~0u, s, 1);
        float p = __expf(s);
        l += p; acc += p * f.y;
    }
    int i = beg;
    for (; i + 1 < end; i += 2) {
        int s0 = g_csr[i], s1 = g_csr[i + 1];
        uint32_t u0 = kvp[(size_t)s0 * kTD + hd];
        uint32_t u1 = kvp[(size_t)s1 * kTD + hd];
        float2 f0 = __half22float2(*reinterpret_cast<const __half2*>(&u0));
        float2 f1 = __half22float2(*reinterpret_cast<const __half2*>(&u1));
        float a = qv * f0.x, b = qv * f1.x;
        a += __shfl_xor_sync(~0u, a, 16); b += __shfl_xor_sync(~0u, b, 16);
        a += __shfl_xor_sync(~0u, a, 8);  b += __shfl_xor_sync(~0u, b, 8);
        a += __shfl_xor_sync(~0u, a, 4);  b += __shfl_xor_sync(~0u, b, 4);
        a += __shfl_xor_sync(~0u, a, 2);  b += __shfl_xor_sync(~0u, b, 2);
        a += __shfl_xor_sync(~0u, a, 1);  b += __shfl_xor_sync(~0u, b, 1);
        float p0 = __expf(a), p1 = __expf(b);
        l += p0 + p1;
        acc += p0 * f0.y + p1 * f1.y;
    }
    if (i < end) {
        int s0 = g_csr[i];
        uint32_t u = kvp[(size_t)s0 * kTD + hd];
        float2 f = __half22float2(*reinterpret_cast<const __half2*>(&u));
        float s = qv * f.x;
        s += __shfl_xor_sync(~0u, s, 16);
        s += __shfl_xor_sync(~0u, s, 8);
        s += __shfl_xor_sync(~0u, s, 4);
        s += __shfl_xor_sync(~0u, s, 2);
        s += __shfl_xor_sync(~0u, s, 1);
        float p = __expf(s);
        l += p; acc += p * f.y;
    }
    g_aggh[node * kTD + hd] = __float2half_rn(acc / l);
}

// ---------------- host ----------------
static inline void gemm(const __half* A, const __half* Bt, const float* bias,
                        float* C, __half* aux, int M, int N, int K, int flags) {
    dim3 g(N / BN, M / BM);
    gemm_tc<<<g, 256>>>(A, Bt, bias, C, aux, M, N, K, flags);
}

extern "C" void kernel_launch(void* const* d_in, const int* in_sizes, int n_in,
                              void* d_out, int out_size) {
    const float* x     = (const float*)d_in[0];
    const int*   ei    = (const int*)  d_in[1];
    const float* w_in  = (const float*)d_in[2];
    const float* b_in  = (const float*)d_in[3];
    const float* ln1_g = (const float*)d_in[4];
    const float* ln1_b = (const float*)d_in[5];
    const float* ln2_g = (const float*)d_in[6];
    const float* ln2_b = (const float*)d_in[7];
    const float* wq = (const float*)d_in[8];  const float* bq = (const float*)d_in[9];
    const float* wk = (const float*)d_in[10]; const float* bk = (const float*)d_in[11];
    const float* wv = (const float*)d_in[12]; const float* bv = (const float*)d_in[13];
    const float* wo = (const float*)d_in[14]; const float* bo = (const float*)d_in[15];
    const float* w1 = (const float*)d_in[16]; const float* b1 = (const float*)d_in[17];
    const float* w2 = (const float*)d_in[18]; const float* b2 = (const float*)d_in[19];
    float* h = (float*)d_out;

    __half *xh, *xnh, *kv, *aggh, *ffnh, *winT, *wqkvT, *woT, *w1T, *w2T;
    float *q, *bqkv;
    int *deg, *fill;
    cudaGetSymbolAddress((void**)&xh,    g_xh);
    cudaGetSymbolAddress((void**)&xnh,   g_xnh);
    cudaGetSymbolAddress((void**)&q,     g_q);
    cudaGetSymbolAddress((void**)&kv,    g_kv);
    cudaGetSymbolAddress((void**)&aggh,  g_aggh);
    cudaGetSymbolAddress((void**)&ffnh,  g_ffnh);
    cudaGetSymbolAddress((void**)&winT,  g_winT);
    cudaGetSymbolAddress((void**)&wqkvT, g_wqkvT);
    cudaGetSymbolAddress((void**)&woT,   g_woT);
    cudaGetSymbolAddress((void**)&w1T,   g_w1T);
    cudaGetSymbolAddress((void**)&w2T,   g_w2T);
    cudaGetSymbolAddress((void**)&bqkv,  g_bqkv);
    cudaGetSymbolAddress((void**)&deg,   g_deg);
    cudaGetSymbolAddress((void**)&fill,  g_fill);

    // ---- CSR by dst ----
    cudaMemsetAsync(deg,  0, kN * sizeof(int));
    cudaMemsetAsync(fill, 0, kN * sizeof(int));
    deg_count_kernel<<<kE / 256, 256>>>(ei);
    prefix_kernel<<<1, 1024>>>();
    scatter_kernel<<<kE / 256, 256>>>(ei);

    // ---- prep: cvt x, transposes (fp16), bias pack ----
    cvt_x<<<kN * kD / 4 / 256, 256>>>(x, xh);
    {
        dim3 b(32, 8);
        transpose_h<<<dim3(kD / 32, kD / 32), b>>>(w_in, winT, kD, kD);
        for (int l = 0; l < kL; ++l) {
            transpose3_h<<<dim3(kTD / 32, kD / 32, 3), b>>>(
                wq + (size_t)l * kD * kTD, wk + (size_t)l * kD * kTD, wv + (size_t)l * kD * kTD,
                wqkvT + (size_t)l * kQKV * kD, kD, kTD);
            transpose_h<<<dim3(kD / 32, kTD / 32), b>>>(wo + (size_t)l * kTD * kD,
                                                        woT + (size_t)l * kD * kTD, kTD, kD);
            transpose_h<<<dim3(kFFN / 32, kD / 32), b>>>(w1 + (size_t)l * kD * kFFN,
                                                         w1T + (size_t)l * kFFN * kD, kD, kFFN);
            transpose_h<<<dim3(kD / 32, kFFN / 32), b>>>(w2 + (size_t)l * kFFN * kD,
                                                         w2T + (size_t)l * kD * kFFN, kFFN, kD);
        }
        pack_bias<<<kL * kQKV / 256, 256>>>(bq, bk, bv);
    }

    // ---- input projection ----
    gemm(xh, winT, b_in, h, nullptr, kN, kD, kD, 0);

    for (int l = 0; l < kL; ++l) {
        ln_kernel<<<kN, 256>>>(h, ln1_g + l * kD, ln1_b + l * kD, xnh);
        gemm(xnh, wqkvT + (size_t)l * kQKV * kD, bqkv + (size_t)l * kQKV,
             q, kv, kN, kQKV, kD, 3);
        attn_kernel<<<kN, 256>>>();
        gemm(aggh, woT + (size_t)l * kD * kTD, bo + (size_t)l * kD,
             h, nullptr, kN, kD, kTD, 1);
        ln_kernel<<<kN, 256>>>(h, ln2_g + l * kD, ln2_b + l * kD, xnh);
        gemm(xnh, w1T + (size_t)l * kFFN * kD, b1 + (size_t)l * kFFN,
             nullptr, ffnh, kN, kFFN, kD, 2);
        gemm(ffnh, w2T + (size_t)l * kD * kFFN, b2 + (size_t)l * kD,
             h, nullptr, kN, kD, kFFN, 1);
    }
}

// round 8
// speedup vs baseline: 3.4315x; 1.1949x over previous
#include <cuda_runtime.h>
#include <cuda_fp16.h>
#include <math.h>
#include <stdint.h>

#define kN   32768
#define kE   (kN * 16)
#define kD   256
#define kH   8
#define kDH  32
#define kTD  256
#define kFFN 1024
#define kL   2
#define kQKV 768

// ---------------- device scratch ----------------
__device__ __half g_xh  [kN * kD];
__device__ __half g_xnh [kN * kD];
__device__ float  g_q   [kN * kTD];
__device__ __half g_kh  [kN * kTD];
__device__ __half g_vh  [kN * kTD];
__device__ __half g_aggh[kN * kTD];
__device__ __half g_ffnh[kN * kFFN];
__device__ __half g_winT [kD * kD];
__device__ __half g_wqkvT[kL * kQKV * kD];
__device__ __half g_woT  [kL * kD * kTD];
__device__ __half g_w1T  [kL * kFFN * kD];
__device__ __half g_w2T  [kL * kD * kFFN];
__device__ float  g_bqkv [kL * kQKV];
__device__ int    g_deg [kN];
__device__ int    g_fill[kN];
__device__ int    g_off [kN + 1];
__device__ int    g_csr [kE];

// ---------------- helpers ----------------
__device__ __forceinline__ void mma_f16(float& d0, float& d1, float& d2, float& d3,
                                        uint32_t a0, uint32_t a1, uint32_t a2, uint32_t a3,
                                        uint32_t b0, uint32_t b1) {
    asm volatile("mma.sync.aligned.m16n8k16.row.col.f32.f16.f16.f32 "
                 "{%0,%1,%2,%3}, {%4,%5,%6,%7}, {%8,%9}, {%0,%1,%2,%3};"
                 : "+f"(d0), "+f"(d1), "+f"(d2), "+f"(d3)
                 : "r"(a0), "r"(a1), "r"(a2), "r"(a3), "r"(b0), "r"(b1));
}
__device__ __forceinline__ float gelu_exact(float x) {
    return 0.5f * x * (1.f + erff(x * 0.7071067811865475f));
}

// ---------------- fp16 mma.sync GEMM: C[M,N] = A[M,K] @ Bt[N,K]^T ---------
// flags: 0 plain fp32 out, 1 residual fp32 out, 2 gelu->fp16 aux,
//        3 qkv pack (q fp32 in C, k in aux, v in aux2)
#define BM 128
#define BN 128
#define BK 32

__global__ void __launch_bounds__(256, 2)
gemm_tc(const __half* __restrict__ A, const __half* __restrict__ Bt,
        const float* __restrict__ bias, float* __restrict__ C,
        __half* __restrict__ aux, __half* __restrict__ aux2,
        int M, int N, int K, int flags) {
    // fragment-major layouts: last dim = regs of ONE lane (contiguous 16B / 8B)
    __shared__ uint32_t As[2][2][8][32][4];    // 16 KB
    __shared__ uint32_t Bs[2][2][16][32][2];   // 16 KB

    int tid = threadIdx.x;
    int lane = tid & 31;
    int wid = tid >> 5;
    int warp_row = wid >> 2;
    int warp_col = wid & 3;
    int row0 = blockIdx.y * BM, col0 = blockIdx.x * BN;

    const __half* Ag = A + (size_t)row0 * K;
    const __half* Bg = Bt + (size_t)col0 * K;

    float acc[4][4][4];
    #pragma unroll
    for (int i = 0; i < 4; ++i)
        #pragma unroll
        for (int j = 0; j < 4; ++j)
            #pragma unroll
            for (int q = 0; q < 4; ++q) acc[i][j][q] = 0.f;

    int nIter = K / BK;
    uint32_t pa[4][2], pb[4][2];

    #pragma unroll
    for (int j = 0; j < 4; ++j) {
        int idx = tid + j * 256;
        int r = idx >> 3, c4 = idx & 7;
        uint2 ua = *reinterpret_cast<const uint2*>(Ag + (size_t)r * K + c4 * 4);
        uint2 ub = *reinterpret_cast<const uint2*>(Bg + (size_t)r * K + c4 * 4);
        pa[j][0] = ua.x; pa[j][1] = ua.y;
        pb[j][0] = ub.x; pb[j][1] = ub.y;
    }
    #pragma unroll
    for (int j = 0; j < 4; ++j) {
        int idx = tid + j * 256;
        int r = idx >> 3, c4 = idx & 7;
        int kc = c4 >> 2;
        int km0 = (c4 & 3) * 4;
        int rega = ((km0 & 8) ? 2 : 0) | ((r & 8) ? 1 : 0);
        int lane0 = ((r & 7) << 2) | ((km0 & 4) >> 1);
        As[0][kc][r >> 4][lane0][rega]     = pa[j][0];
        As[0][kc][r >> 4][lane0 + 1][rega] = pa[j][1];
        int regb = (km0 & 8) ? 1 : 0;
        Bs[0][kc][r >> 3][lane0][regb]     = pb[j][0];
        Bs[0][kc][r >> 3][lane0 + 1][regb] = pb[j][1];
    }
    __syncthreads();

    for (int it = 0; it < nIter; ++it) {
        int s = it & 1;
        bool more = (it + 1 < nIter);
        if (more) {
            int kk = (it + 1) * BK;
            #pragma unroll
            for (int j = 0; j < 4; ++j) {
                int idx = tid + j * 256;
                int r = idx >> 3, c4 = idx & 7;
                uint2 ua = *reinterpret_cast<const uint2*>(Ag + (size_t)r * K + kk + c4 * 4);
                uint2 ub = *reinterpret_cast<const uint2*>(Bg + (size_t)r * K + kk + c4 * 4);
                pa[j][0] = ua.x; pa[j][1] = ua.y;
                pb[j][0] = ub.x; pb[j][1] = ub.y;
            }
        }
        #pragma unroll
        for (int kc = 0; kc < 2; ++kc) {
            uint4 af[4];
            uint2 bf[4];
            #pragma unroll
            for (int mt = 0; mt < 4; ++mt)
                af[mt] = *reinterpret_cast<const uint4*>(&As[s][kc][warp_row * 4 + mt][lane][0]);
            #pragma unroll
            for (int nt = 0; nt < 4; ++nt)
                bf[nt] = *reinterpret_cast<const uint2*>(&Bs[s][kc][warp_col * 4 + nt][lane][0]);
            #pragma unroll
            for (int mt = 0; mt < 4; ++mt)
                #pragma unroll
                for (int nt = 0; nt < 4; ++nt)
                    mma_f16(acc[mt][nt][0], acc[mt][nt][1], acc[mt][nt][2], acc[mt][nt][3],
                            af[mt].x, af[mt].y, af[mt].z, af[mt].w,
                            bf[nt].x, bf[nt].y);
        }
        if (more) {
            int sn = s ^ 1;
            #pragma unroll
            for (int j = 0; j < 4; ++j) {
                int idx = tid + j * 256;
                int r = idx >> 3, c4 = idx & 7;
                int kc = c4 >> 2;
                int km0 = (c4 & 3) * 4;
                int rega = ((km0 & 8) ? 2 : 0) | ((r & 8) ? 1 : 0);
                int lane0 = ((r & 7) << 2) | ((km0 & 4) >> 1);
                As[sn][kc][r >> 4][lane0][rega]     = pa[j][0];
                As[sn][kc][r >> 4][lane0 + 1][rega] = pa[j][1];
                int regb = (km0 & 8) ? 1 : 0;
                Bs[sn][kc][r >> 3][lane0][regb]     = pb[j][0];
                Bs[sn][kc][r >> 3][lane0 + 1][regb] = pb[j][1];
            }
            __syncthreads();
        }
    }

    // ---- epilogue ----
    int g = lane >> 2, tg = lane & 3;
    bool isq = (col0 < 256);
    bool isv = (col0 >= 512);
    #pragma unroll
    for (int mt = 0; mt < 4; ++mt) {
        int rbase = row0 + warp_row * 64 + mt * 16 + g;
        #pragma unroll
        for (int nt = 0; nt < 4; ++nt) {
            int c = col0 + warp_col * 32 + nt * 8 + tg * 2;
            float2 bs = *reinterpret_cast<const float2*>(&bias[c]);
            float v0 = acc[mt][nt][0] + bs.x;
            float v1 = acc[mt][nt][1] + bs.y;
            float v2 = acc[mt][nt][2] + bs.x;
            float v3 = acc[mt][nt][3] + bs.y;
            if (flags == 2) {
                v0 = gelu_exact(v0); v1 = gelu_exact(v1);
                v2 = gelu_exact(v2); v3 = gelu_exact(v3);
                *reinterpret_cast<__half2*>(aux + (size_t)rbase * N + c)       = __floats2half2_rn(v0, v1);
                *reinterpret_cast<__half2*>(aux + (size_t)(rbase + 8) * N + c) = __floats2half2_rn(v2, v3);
            } else if (flags == 3) {
                if (isq) {
                    float2 w0 = {v0, v1}, w1 = {v2, v3};
                    *reinterpret_cast<float2*>(C + (size_t)rbase * kTD + c) = w0;
                    *reinterpret_cast<float2*>(C + (size_t)(rbase + 8) * kTD + c) = w1;
                } else {
                    __half* dst = isv ? aux2 : aux;
                    int cm = c - (isv ? 512 : 256);
                    *reinterpret_cast<__half2*>(dst + (size_t)rbase * kTD + cm)       = __floats2half2_rn(v0, v1);
                    *reinterpret_cast<__half2*>(dst + (size_t)(rbase + 8) * kTD + cm) = __floats2half2_rn(v2, v3);
                }
            } else {
                float2* cp0 = reinterpret_cast<float2*>(C + (size_t)rbase * N + c);
                float2* cp1 = reinterpret_cast<float2*>(C + (size_t)(rbase + 8) * N + c);
                if (flags == 1) {
                    float2 o0 = *cp0, o1 = *cp1;
                    v0 += o0.x; v1 += o0.y; v2 += o1.x; v3 += o1.y;
                }
                float2 r0 = {v0, v1}, r1 = {v2, v3};
                *cp0 = r0;
                *cp1 = r1;
            }
        }
    }
}

// ---------------- transpose + fp32->fp16 ----------------
__global__ void transpose_h(const float* __restrict__ src, __half* __restrict__ dst,
                            int R, int C) {
    __shared__ float t[32][33];
    int bx = blockIdx.x * 32, by = blockIdx.y * 32;
    int x = bx + threadIdx.x;
    #pragma unroll
    for (int j = 0; j < 32; j += 8)
        t[threadIdx.y + j][threadIdx.x] = src[(size_t)(by + threadIdx.y + j) * C + x];
    __syncthreads();
    int xo = by + threadIdx.x;
    #pragma unroll
    for (int j = 0; j < 32; j += 8)
        dst[(size_t)(bx + threadIdx.y + j) * R + xo] = __float2half_rn(t[threadIdx.x][threadIdx.y + j]);
}
__global__ void transpose3_h(const float* s0, const float* s1, const float* s2,
                             __half* __restrict__ dst, int R, int C) {
    __shared__ float t[32][33];
    const float* src = (blockIdx.z == 0) ? s0 : (blockIdx.z == 1) ? s1 : s2;
    __half* d = dst + (size_t)blockIdx.z * C * R;
    int bx = blockIdx.x * 32, by = blockIdx.y * 32;
    int x = bx + threadIdx.x;
    #pragma unroll
    for (int j = 0; j < 32; j += 8)
        t[threadIdx.y + j][threadIdx.x] = src[(size_t)(by + threadIdx.y + j) * C + x];
    __syncthreads();
    int xo = by + threadIdx.x;
    #pragma unroll
    for (int j = 0; j < 32; j += 8)
        d[(size_t)(bx + threadIdx.y + j) * R + xo] = __float2half_rn(t[threadIdx.x][threadIdx.y + j]);
}

__global__ void cvt_x(const float* __restrict__ x, __half* __restrict__ xh) {
    int i = blockIdx.x * 256 + threadIdx.x;
    float4 v = reinterpret_cast<const float4*>(x)[i];
    __half2 h0 = __floats2half2_rn(v.x, v.y);
    __half2 h1 = __floats2half2_rn(v.z, v.w);
    uint2 u = {*reinterpret_cast<uint32_t*>(&h0), *reinterpret_cast<uint32_t*>(&h1)};
    reinterpret_cast<uint2*>(xh)[i] = u;
}

__global__ void pack_bias(const float* bq, const float* bk, const float* bv) {
    int t = blockIdx.x * 256 + threadIdx.x;
    int l = t / kQKV, r = t % kQKV;
    const float* s = (r < 256) ? bq + l * kTD + r
                   : (r < 512) ? bk + l * kTD + (r - 256)
                               : bv + l * kTD + (r - 512);
    g_bqkv[t] = *s;
}

// ---------------- CSR build ----------------
__global__ void deg_count_kernel(const int* __restrict__ ei) {
    int e = blockIdx.x * 256 + threadIdx.x;
    if (e < kE) atomicAdd(&g_deg[ei[kE + e]], 1);
}
__global__ void prefix_kernel() {
    __shared__ int sums[1024];
    int t = threadIdx.x;
    int base = t * 32;
    int s = 0;
    #pragma unroll 4
    for (int i = 0; i < 32; ++i) s += g_deg[base + i];
    sums[t] = s;
    __syncthreads();
    for (int o = 1; o < 1024; o <<= 1) {
        int v = (t >= o) ? sums[t - o] : 0;
        __syncthreads();
        sums[t] += v;
        __syncthreads();
    }
    int run = sums[t] - s;
    for (int i = 0; i < 32; ++i) { g_off[base + i] = run; run += g_deg[base + i]; }
    if (t == 1023) g_off[kN] = run;
}
__global__ void scatter_kernel(const int* __restrict__ ei) {
    int e = blockIdx.x * 256 + threadIdx.x;
    if (e < kE) {
        int d = ei[kE + e];
        int pos = g_off[d] + atomicAdd(&g_fill[d], 1);
        g_csr[pos] = ei[e];
    }
}

// ---------------- LayerNorm (fp32 in, fp16 out) ----------------
__global__ void ln_kernel(const float* __restrict__ x, const float* __restrict__ g,
                          const float* __restrict__ b, __half* __restrict__ y) {
    int t = threadIdx.x;
    int row = blockIdx.x;
    float v = x[(size_t)row * kD + t];
    __shared__ float sh[8];
    float s = v;
    #pragma unroll
    for (int o = 16; o; o >>= 1) s += __shfl_xor_sync(0xffffffffu, s, o);
    if ((t & 31) == 0) sh[t >> 5] = s;
    __syncthreads();
    float mean = (sh[0]+sh[1]+sh[2]+sh[3]+sh[4]+sh[5]+sh[6]+sh[7]) * (1.f / kD);
    float d = v - mean;
    float sq = d * d;
    __syncthreads();
    #pragma unroll
    for (int o = 16; o; o >>= 1) sq += __shfl_xor_sync(0xffffffffu, sq, o);
    if ((t & 31) == 0) sh[t >> 5] = sq;
    __syncthreads();
    float var = (sh[0]+sh[1]+sh[2]+sh[3]+sh[4]+sh[5]+sh[6]+sh[7]) * (1.f / kD);
    y[(size_t)row * kD + t] = __float2half_rn(d * rsqrtf(var + 1e-5f) * g[t] + b[t]);
}

// ---------------- Edge attention: warp = 2 heads, lane = 2 dims -----------
__global__ void __launch_bounds__(128)
attn_kernel() {
    int tid = threadIdx.x;
    int lane = tid & 31;
    int w = tid >> 5;                // warp 0..3
    int node = blockIdx.x;
    int head = w * 2 + (lane >> 4);  // 2 heads per warp
    int j = lane & 15;               // dim pair index
    int hd0 = head * kDH + 2 * j;

    int beg = g_off[node], end = g_off[node + 1];
    __half2* aggp = reinterpret_cast<__half2*>(g_aggh);
    int outi = (node * kTD + hd0) >> 1;
    if (beg == end) { aggp[outi] = __floats2half2_rn(0.f, 0.f); return; }

    float2 qf = *reinterpret_cast<const float2*>(g_q + node * kTD + hd0);
    float qv0 = qf.x * 0.17677669529663687f;
    float qv1 = qf.y * 0.17677669529663687f;
    const __half2* kp = reinterpret_cast<const __half2*>(g_kh);
    const __half2* vp = reinterpret_cast<const __half2*>(g_vh);

    float l = 0.f, acc0 = 0.f, acc1 = 0.f;
    // self edge
    {
        float2 kk = __half22float2(kp[(size_t)(node * kTD + hd0) >> 1]);
        float2 vv = __half22float2(vp[(size_t)(node * kTD + hd0) >> 1]);
        float s = qv0 * kk.x + qv1 * kk.y;
        s += __shfl_xor_sync(~0u, s, 8);
        s += __shfl_xor_sync(~0u, s, 4);
        s += __shfl_xor_sync(~0u, s, 2);
        s += __shfl_xor_sync(~0u, s, 1);
        float p = __expf(s);
        l += p; acc0 += p * vv.x; acc1 += p * vv.y;
    }
    int i = beg;
    for (; i + 1 < end; i += 2) {
        int s0 = g_csr[i], s1 = g_csr[i + 1];
        size_t i0 = ((size_t)s0 * kTD + hd0) >> 1;
        size_t i1 = ((size_t)s1 * kTD + hd0) >> 1;
        float2 k0 = __half22float2(kp[i0]);
        float2 k1 = __half22float2(kp[i1]);
        float2 v0 = __half22float2(vp[i0]);
        float2 v1 = __half22float2(vp[i1]);
        float a = qv0 * k0.x + qv1 * k0.y;
        float b = qv0 * k1.x + qv1 * k1.y;
        a += __shfl_xor_sync(~0u, a, 8); b += __shfl_xor_sync(~0u, b, 8);
        a += __shfl_xor_sync(~0u, a, 4); b += __shfl_xor_sync(~0u, b, 4);
        a += __shfl_xor_sync(~0u, a, 2); b += __shfl_xor_sync(~0u, b, 2);
        a += __shfl_xor_sync(~0u, a, 1); b += __shfl_xor_sync(~0u, b, 1);
        float p0 = __expf(a), p1 = __expf(b);
        l += p0 + p1;
        acc0 += p0 * v0.x + p1 * v1.x;
        acc1 += p0 * v0.y + p1 * v1.y;
    }
    if (i < end) {
        int s0 = g_csr[i];
        size_t i0 = ((size_t)s0 * kTD + hd0) >> 1;
        float2 kk = __half22float2(kp[i0]);
        float2 vv = __half22float2(vp[i0]);
        float s = qv0 * kk.x + qv1 * kk.y;
        s += __shfl_xor_sync(~0u, s, 8);
        s += __shfl_xor_sync(~0u, s, 4);
        s += __shfl_xor_sync(~0u, s, 2);
        s += __shfl_xor_sync(~0u, s, 1);
        float p = __expf(s);
        l += p; acc0 += p * vv.x; acc1 += p * vv.y;
    }
    float inv = 1.f / l;
    aggp[outi] = __floats2half2_rn(acc0 * inv, acc1 * inv);
}

// ---------------- host ----------------
static inline void gemm(const __half* A, const __half* Bt, const float* bias,
                        float* C, __half* aux, __half* aux2,
                        int M, int N, int K, int flags) {
    dim3 g(N / BN, M / BM);
    gemm_tc<<<g, 256>>>(A, Bt, bias, C, aux, aux2, M, N, K, flags);
}

extern "C" void kernel_launch(void* const* d_in, const int* in_sizes, int n_in,
                              void* d_out, int out_size) {
    const float* x     = (const float*)d_in[0];
    const int*   ei    = (const int*)  d_in[1];
    const float* w_in  = (const float*)d_in[2];
    const float* b_in  = (const float*)d_in[3];
    const float* ln1_g = (const float*)d_in[4];
    const float* ln1_b = (const float*)d_in[5];
    const float* ln2_g = (const float*)d_in[6];
    const float* ln2_b = (const float*)d_in[7];
    const float* wq = (const float*)d_in[8];  const float* bq = (const float*)d_in[9];
    const float* wk = (const float*)d_in[10]; const float* bk = (const float*)d_in[11];
    const float* wv = (const float*)d_in[12]; const float* bv = (const float*)d_in[13];
    const float* wo = (const float*)d_in[14]; const float* bo = (const float*)d_in[15];
    const float* w1 = (const float*)d_in[16]; const float* b1 = (const float*)d_in[17];
    const float* w2 = (const float*)d_in[18]; const float* b2 = (const float*)d_in[19];
    float* h = (float*)d_out;

    __half *xh, *xnh, *kh, *vh, *aggh, *ffnh, *winT, *wqkvT, *woT, *w1T, *w2T;
    float *q, *bqkv;
    int *deg, *fill;
    cudaGetSymbolAddress((void**)&xh,    g_xh);
    cudaGetSymbolAddress((void**)&xnh,   g_xnh);
    cudaGetSymbolAddress((void**)&q,     g_q);
    cudaGetSymbolAddress((void**)&kh,    g_kh);
    cudaGetSymbolAddress((void**)&vh,    g_vh);
    cudaGetSymbolAddress((void**)&aggh,  g_aggh);
    cudaGetSymbolAddress((void**)&ffnh,  g_ffnh);
    cudaGetSymbolAddress((void**)&winT,  g_winT);
    cudaGetSymbolAddress((void**)&wqkvT, g_wqkvT);
    cudaGetSymbolAddress((void**)&woT,   g_woT);
    cudaGetSymbolAddress((void**)&w1T,   g_w1T);
    cudaGetSymbolAddress((void**)&w2T,   g_w2T);
    cudaGetSymbolAddress((void**)&bqkv,  g_bqkv);
    cudaGetSymbolAddress((void**)&deg,   g_deg);
    cudaGetSymbolAddress((void**)&fill,  g_fill);

    // ---- CSR by dst ----
    cudaMemsetAsync(deg,  0, kN * sizeof(int));
    cudaMemsetAsync(fill, 0, kN * sizeof(int));
    deg_count_kernel<<<kE / 256, 256>>>(ei);
    prefix_kernel<<<1, 1024>>>();
    scatter_kernel<<<kE / 256, 256>>>(ei);

    // ---- prep ----
    cvt_x<<<kN * kD / 4 / 256, 256>>>(x, xh);
    {
        dim3 b(32, 8);
        transpose_h<<<dim3(kD / 32, kD / 32), b>>>(w_in, winT, kD, kD);
        for (int l = 0; l < kL; ++l) {
            transpose3_h<<<dim3(kTD / 32, kD / 32, 3), b>>>(
                wq + (size_t)l * kD * kTD, wk + (size_t)l * kD * kTD, wv + (size_t)l * kD * kTD,
                wqkvT + (size_t)l * kQKV * kD, kD, kTD);
            transpose_h<<<dim3(kD / 32, kTD / 32), b>>>(wo + (size_t)l * kTD * kD,
                                                        woT + (size_t)l * kD * kTD, kTD, kD);
            transpose_h<<<dim3(kFFN / 32, kD / 32), b>>>(w1 + (size_t)l * kD * kFFN,
                                                         w1T + (size_t)l * kFFN * kD, kD, kFFN);
            transpose_h<<<dim3(kD / 32, kFFN / 32), b>>>(w2 + (size_t)l * kFFN * kD,
                                                         w2T + (size_t)l * kD * kFFN, kFFN, kD);
        }
        pack_bias<<<kL * kQKV / 256, 256>>>(bq, bk, bv);
    }

    // ---- input projection ----
    gemm(xh, winT, b_in, h, nullptr, nullptr, kN, kD, kD, 0);

    for (int l = 0; l < kL; ++l) {
        ln_kernel<<<kN, 256>>>(h, ln1_g + l * kD, ln1_b + l * kD, xnh);
        gemm(xnh, wqkvT + (size_t)l * kQKV * kD, bqkv + (size_t)l * kQKV,
             q, kh, vh, kN, kQKV, kD, 3);
        attn_kernel<<<kN, 128>>>();
        gemm(aggh, woT + (size_t)l * kD * kTD, bo + (size_t)l * kD,
             h, nullptr, nullptr, kN, kD, kTD, 1);
        ln_kernel<<<kN, 256>>>(h, ln2_g + l * kD, ln2_b + l * kD, xnh);
        gemm(xnh, w1T + (size_t)l * kFFN * kD, b1 + (size_t)l * kFFN,
             nullptr, ffnh, nullptr, kN, kFFN, kD, 2);
        gemm(ffnh, w2T + (size_t)l * kD * kFFN, b2 + (size_t)l * kD,
             h, nullptr, nullptr, kN, kD, kFFN, 1);
    }
}

// round 9
// speedup vs baseline: 3.8105x; 1.1104x over previous
#include <cuda_runtime.h>
#include <cuda_fp16.h>
#include <math.h>
#include <stdint.h>

#define kN   32768
#define kE   (kN * 16)
#define kD   256
#define kH   8
#define kDH  32
#define kTD  256
#define kFFN 1024
#define kL   2
#define kQKV 768

// ---------------- device scratch ----------------
__device__ __half g_xh  [kN * kD];
__device__ __half g_xnh [kN * kD];
__device__ float  g_q   [kN * kTD];
__device__ __half g_kh  [kN * kTD];
__device__ __half g_vh  [kN * kTD];
__device__ __half g_aggh[kN * kTD];
__device__ __half g_ffnh[kN * kFFN];
__device__ __half g_winT [kD * kD];
__device__ __half g_wqkvT[kL * kQKV * kD];
__device__ __half g_woT  [kL * kD * kTD];
__device__ __half g_w1T  [kL * kFFN * kD];
__device__ __half g_w2T  [kL * kD * kFFN];
__device__ float  g_bqkv [kL * kQKV];
__device__ int    g_deg [kN];
__device__ int    g_fill[kN];
__device__ int    g_off [kN + 1];
__device__ int    g_csr [kE];

// ---------------- helpers ----------------
__device__ __forceinline__ uint32_t smem_u32(const void* p) {
    uint32_t a;
    asm("{ .reg .u64 t; cvta.to.shared.u64 t, %1; cvt.u32.u64 %0, t; }" : "=r"(a) : "l"(p));
    return a;
}
__device__ __forceinline__ void mma_f16(float& d0, float& d1, float& d2, float& d3,
                                        uint32_t a0, uint32_t a1, uint32_t a2, uint32_t a3,
                                        uint32_t b0, uint32_t b1) {
    asm volatile("mma.sync.aligned.m16n8k16.row.col.f32.f16.f16.f32 "
                 "{%0,%1,%2,%3}, {%4,%5,%6,%7}, {%8,%9}, {%0,%1,%2,%3};"
                 : "+f"(d0), "+f"(d1), "+f"(d2), "+f"(d3)
                 : "r"(a0), "r"(a1), "r"(a2), "r"(a3), "r"(b0), "r"(b1));
}
__device__ __forceinline__ void ldsm_x4(uint4& r, uint32_t addr) {
    asm volatile("ldmatrix.sync.aligned.m8n8.x4.shared.b16 {%0,%1,%2,%3}, [%4];"
                 : "=r"(r.x), "=r"(r.y), "=r"(r.z), "=r"(r.w) : "r"(addr));
}
__device__ __forceinline__ void cp16(uint32_t saddr, const void* gaddr) {
    asm volatile("cp.async.cg.shared.global [%0], [%1], 16;" :: "r"(saddr), "l"(gaddr));
}
__device__ __forceinline__ float gelu_exact(float x) {
    return 0.5f * x * (1.f + erff(x * 0.7071067811865475f));
}

// ---------------- fp16 cp.async+ldmatrix GEMM: C = A[M,K] @ Bt[N,K]^T -----
// flags: 0 plain fp32 out, 1 residual fp32 out, 2 gelu->fp16 aux,
//        3 qkv pack (q fp32 in C, k in aux, v in aux2)
#define BM 128
#define BN 128
#define BK 32
#define ATILE_B (BM * BK * 2)            // 8192
#define STAGE_B (ATILE_B + BN * BK * 2)  // 16384
#define NSTAGE 4
#define DSMEM (NSTAGE * STAGE_B)         // 65536

__global__ void __launch_bounds__(256, 2)
gemm_tc(const __half* __restrict__ A, const __half* __restrict__ Bt,
        const float* __restrict__ bias, float* __restrict__ C,
        __half* __restrict__ aux, __half* __restrict__ aux2,
        int M, int N, int K, int flags) {
    extern __shared__ char dsm[];
    uint32_t sbase = smem_u32(dsm);

    int tid = threadIdx.x;
    int lane = tid & 31;
    int wid = tid >> 5;
    int warp_row = wid >> 2;
    int warp_col = wid & 3;
    int row0 = blockIdx.y * BM, col0 = blockIdx.x * BN;

    const __half* Ag = A + (size_t)row0 * K;
    const __half* Bg = Bt + (size_t)col0 * K;

    // copy indices: thread t copies chunks 2t, 2t+1 of A and of B
    int id0 = tid * 2;
    int crow0 = id0 >> 2,       cc0 = id0 & 3;
    int crow1 = (id0 + 1) >> 2, cc1 = (id0 + 1) & 3;
    int cs0 = cc0 ^ ((crow0 >> 1) & 3);
    int cs1 = cc1 ^ ((crow1 >> 1) & 3);
    uint32_t sA0 = crow0 * 64 + cs0 * 16;
    uint32_t sA1 = crow1 * 64 + cs1 * 16;
    size_t gA0 = (size_t)crow0 * K + cc0 * 8;
    size_t gA1 = (size_t)crow1 * K + cc1 * 8;

    // fragment read indices
    int lane_r = lane & 15;
    int lane_c = lane >> 4;
    int xorv = (lane_r >> 1) & 3;

    float acc[4][4][4];
    #pragma unroll
    for (int i = 0; i < 4; ++i)
        #pragma unroll
        for (int j = 0; j < 4; ++j)
            #pragma unroll
            for (int q = 0; q < 4; ++q) acc[i][j][q] = 0.f;

    int nIter = K / BK;

    // prologue: issue 3 stages
    #pragma unroll
    for (int s = 0; s < 3; ++s) {
        uint32_t Ab = sbase + s * STAGE_B;
        uint32_t Bb = Ab + ATILE_B;
        int kk = s * BK;
        cp16(Ab + sA0, Ag + gA0 + kk);
        cp16(Ab + sA1, Ag + gA1 + kk);
        cp16(Bb + sA0, Bg + gA0 + kk);
        cp16(Bb + sA1, Bg + gA1 + kk);
        asm volatile("cp.async.commit_group;");
    }

    for (int it = 0; it < nIter; ++it) {
        asm volatile("cp.async.wait_group 2;");
        __syncthreads();
        uint32_t Ab = sbase + (it & 3) * STAGE_B;
        uint32_t Bb = Ab + ATILE_B;

        #pragma unroll
        for (int kc = 0; kc < 2; ++kc) {
            uint32_t cs = (uint32_t)(((kc * 2 + lane_c) ^ xorv) * 16);
            uint4 af[4], bm[2];
            #pragma unroll
            for (int mt = 0; mt < 4; ++mt)
                ldsm_x4(af[mt], Ab + (uint32_t)(warp_row * 64 + mt * 16 + lane_r) * 64 + cs);
            #pragma unroll
            for (int ntp = 0; ntp < 2; ++ntp)
                ldsm_x4(bm[ntp], Bb + (uint32_t)(warp_col * 32 + ntp * 16 + lane_r) * 64 + cs);
            #pragma unroll
            for (int mt = 0; mt < 4; ++mt) {
                mma_f16(acc[mt][0][0], acc[mt][0][1], acc[mt][0][2], acc[mt][0][3],
                        af[mt].x, af[mt].y, af[mt].z, af[mt].w, bm[0].x, bm[0].z);
                mma_f16(acc[mt][1][0], acc[mt][1][1], acc[mt][1][2], acc[mt][1][3],
                        af[mt].x, af[mt].y, af[mt].z, af[mt].w, bm[0].y, bm[0].w);
                mma_f16(acc[mt][2][0], acc[mt][2][1], acc[mt][2][2], acc[mt][2][3],
                        af[mt].x, af[mt].y, af[mt].z, af[mt].w, bm[1].x, bm[1].z);
                mma_f16(acc[mt][3][0], acc[mt][3][1], acc[mt][3][2], acc[mt][3][3],
                        af[mt].x, af[mt].y, af[mt].z, af[mt].w, bm[1].y, bm[1].w);
            }
        }
        if (it + 3 < nIter) {
            uint32_t Aw = sbase + ((it + 3) & 3) * STAGE_B;
            uint32_t Bw = Aw + ATILE_B;
            int kk = (it + 3) * BK;
            cp16(Aw + sA0, Ag + gA0 + kk);
            cp16(Aw + sA1, Ag + gA1 + kk);
            cp16(Bw + sA0, Bg + gA0 + kk);
            cp16(Bw + sA1, Bg + gA1 + kk);
        }
        asm volatile("cp.async.commit_group;");
    }

    // ---- epilogue ----
    int g = lane >> 2, tg = lane & 3;
    bool isq = (col0 < 256);
    bool isv = (col0 >= 512);
    #pragma unroll
    for (int mt = 0; mt < 4; ++mt) {
        int rbase = row0 + warp_row * 64 + mt * 16 + g;
        #pragma unroll
        for (int nt = 0; nt < 4; ++nt) {
            int c = col0 + warp_col * 32 + nt * 8 + tg * 2;
            float2 bs = *reinterpret_cast<const float2*>(&bias[c]);
            float v0 = acc[mt][nt][0] + bs.x;
            float v1 = acc[mt][nt][1] + bs.y;
            float v2 = acc[mt][nt][2] + bs.x;
            float v3 = acc[mt][nt][3] + bs.y;
            if (flags == 2) {
                v0 = gelu_exact(v0); v1 = gelu_exact(v1);
                v2 = gelu_exact(v2); v3 = gelu_exact(v3);
                *reinterpret_cast<__half2*>(aux + (size_t)rbase * N + c)       = __floats2half2_rn(v0, v1);
                *reinterpret_cast<__half2*>(aux + (size_t)(rbase + 8) * N + c) = __floats2half2_rn(v2, v3);
            } else if (flags == 3) {
                if (isq) {
                    float2 w0 = {v0, v1}, w1 = {v2, v3};
                    *reinterpret_cast<float2*>(C + (size_t)rbase * kTD + c) = w0;
                    *reinterpret_cast<float2*>(C + (size_t)(rbase + 8) * kTD + c) = w1;
                } else {
                    __half* dst = isv ? aux2 : aux;
                    int cm = c - (isv ? 512 : 256);
                    *reinterpret_cast<__half2*>(dst + (size_t)rbase * kTD + cm)       = __floats2half2_rn(v0, v1);
                    *reinterpret_cast<__half2*>(dst + (size_t)(rbase + 8) * kTD + cm) = __floats2half2_rn(v2, v3);
                }
            } else {
                float2* cp0 = reinterpret_cast<float2*>(C + (size_t)rbase * N + c);
                float2* cp1 = reinterpret_cast<float2*>(C + (size_t)(rbase + 8) * N + c);
                if (flags == 1) {
                    float2 o0 = *cp0, o1 = *cp1;
                    v0 += o0.x; v1 += o0.y; v2 += o1.x; v3 += o1.y;
                }
                float2 r0 = {v0, v1}, r1 = {v2, v3};
                *cp0 = r0;
                *cp1 = r1;
            }
        }
    }
}

// ---------------- transpose + fp32->fp16 ----------------
__global__ void transpose_h(const float* __restrict__ src, __half* __restrict__ dst,
                            int R, int C) {
    __shared__ float t[32][33];
    int bx = blockIdx.x * 32, by = blockIdx.y * 32;
    int x = bx + threadIdx.x;
    #pragma unroll
    for (int j = 0; j < 32; j += 8)
        t[threadIdx.y + j][threadIdx.x] = src[(size_t)(by + threadIdx.y + j) * C + x];
    __syncthreads();
    int xo = by + threadIdx.x;
    #pragma unroll
    for (int j = 0; j < 32; j += 8)
        dst[(size_t)(bx + threadIdx.y + j) * R + xo] = __float2half_rn(t[threadIdx.x][threadIdx.y + j]);
}
__global__ void transpose3_h(const float* s0, const float* s1, const float* s2,
                             __half* __restrict__ dst, int R, int C) {
    __shared__ float t[32][33];
    const float* src = (blockIdx.z == 0) ? s0 : (blockIdx.z == 1) ? s1 : s2;
    __half* d = dst + (size_t)blockIdx.z * C * R;
    int bx = blockIdx.x * 32, by = blockIdx.y * 32;
    int x = bx + threadIdx.x;
    #pragma unroll
    for (int j = 0; j < 32; j += 8)
        t[threadIdx.y + j][threadIdx.x] = src[(size_t)(by + threadIdx.y + j) * C + x];
    __syncthreads();
    int xo = by + threadIdx.x;
    #pragma unroll
    for (int j = 0; j < 32; j += 8)
        d[(size_t)(bx + threadIdx.y + j) * R + xo] = __float2half_rn(t[threadIdx.x][threadIdx.y + j]);
}

__global__ void cvt_x(const float* __restrict__ x, __half* __restrict__ xh) {
    int i = blockIdx.x * 256 + threadIdx.x;
    float4 v = reinterpret_cast<const float4*>(x)[i];
    __half2 h0 = __floats2half2_rn(v.x, v.y);
    __half2 h1 = __floats2half2_rn(v.z, v.w);
    uint2 u = {*reinterpret_cast<uint32_t*>(&h0), *reinterpret_cast<uint32_t*>(&h1)};
    reinterpret_cast<uint2*>(xh)[i] = u;
}

__global__ void pack_bias(const float* bq, const float* bk, const float* bv) {
    int t = blockIdx.x * 256 + threadIdx.x;
    int l = t / kQKV, r = t % kQKV;
    const float* s = (r < 256) ? bq + l * kTD + r
                   : (r < 512) ? bk + l * kTD + (r - 256)
                               : bv + l * kTD + (r - 512);
    g_bqkv[t] = *s;
}

// ---------------- CSR build ----------------
__global__ void deg_count_kernel(const int* __restrict__ ei) {
    int e = blockIdx.x * 256 + threadIdx.x;
    if (e < kE) atomicAdd(&g_deg[ei[kE + e]], 1);
}
__global__ void prefix_kernel() {
    __shared__ int sums[1024];
    int t = threadIdx.x;
    int base = t * 32;
    int s = 0;
    #pragma unroll 4
    for (int i = 0; i < 32; ++i) s += g_deg[base + i];
    sums[t] = s;
    __syncthreads();
    for (int o = 1; o < 1024; o <<= 1) {
        int v = (t >= o) ? sums[t - o] : 0;
        __syncthreads();
        sums[t] += v;
        __syncthreads();
    }
    int run = sums[t] - s;
    for (int i = 0; i < 32; ++i) { g_off[base + i] = run; run += g_deg[base + i]; }
    if (t == 1023) g_off[kN] = run;
}
__global__ void scatter_kernel(const int* __restrict__ ei) {
    int e = blockIdx.x * 256 + threadIdx.x;
    if (e < kE) {
        int d = ei[kE + e];
        int pos = g_off[d] + atomicAdd(&g_fill[d], 1);
        g_csr[pos] = ei[e];
    }
}

// ---------------- LayerNorm (fp32 in, fp16 out) ----------------
__global__ void ln_kernel(const float* __restrict__ x, const float* __restrict__ g,
                          const float* __restrict__ b, __half* __restrict__ y) {
    int t = threadIdx.x;
    int row = blockIdx.x;
    float v = x[(size_t)row * kD + t];
    __shared__ float sh[8];
    float s = v;
    #pragma unroll
    for (int o = 16; o; o >>= 1) s += __shfl_xor_sync(0xffffffffu, s, o);
    if ((t & 31) == 0) sh[t >> 5] = s;
    __syncthreads();
    float mean = (sh[0]+sh[1]+sh[2]+sh[3]+sh[4]+sh[5]+sh[6]+sh[7]) * (1.f / kD);
    float d = v - mean;
    float sq = d * d;
    __syncthreads();
    #pragma unroll
    for (int o = 16; o; o >>= 1) sq += __shfl_xor_sync(0xffffffffu, sq, o);
    if ((t & 31) == 0) sh[t >> 5] = sq;
    __syncthreads();
    float var = (sh[0]+sh[1]+sh[2]+sh[3]+sh[4]+sh[5]+sh[6]+sh[7]) * (1.f / kD);
    y[(size_t)row * kD + t] = __float2half_rn(d * rsqrtf(var + 1e-5f) * g[t] + b[t]);
}

// ---------------- Edge attention: warp = 2 heads, lane = 2 dims -----------
__global__ void __launch_bounds__(128)
attn_kernel() {
    int tid = threadIdx.x;
    int lane = tid & 31;
    int w = tid >> 5;
    int node = blockIdx.x;
    int head = w * 2 + (lane >> 4);
    int j = lane & 15;
    int hd0 = head * kDH + 2 * j;

    int beg = g_off[node], end = g_off[node + 1];
    __half2* aggp = reinterpret_cast<__half2*>(g_aggh);
    int outi = (node * kTD + hd0) >> 1;
    if (beg == end) { aggp[outi] = __floats2half2_rn(0.f, 0.f); return; }

    float2 qf = *reinterpret_cast<const float2*>(g_q + node * kTD + hd0);
    float qv0 = qf.x * 0.17677669529663687f;
    float qv1 = qf.y * 0.17677669529663687f;
    const __half2* kp = reinterpret_cast<const __half2*>(g_kh);
    const __half2* vp = reinterpret_cast<const __half2*>(g_vh);

    float l = 0.f, acc0 = 0.f, acc1 = 0.f;
    {
        float2 kk = __half22float2(kp[(size_t)(node * kTD + hd0) >> 1]);
        float2 vv = __half22float2(vp[(size_t)(node * kTD + hd0) >> 1]);
        float s = qv0 * kk.x + qv1 * kk.y;
        s += __shfl_xor_sync(~0u, s, 8);
        s += __shfl_xor_sync(~0u, s, 4);
        s += __shfl_xor_sync(~0u, s, 2);
        s += __shfl_xor_sync(~0u, s, 1);
        float p = __expf(s);
        l += p; acc0 += p * vv.x; acc1 += p * vv.y;
    }
    int i = beg;
    for (; i + 1 < end; i += 2) {
        int s0 = g_csr[i], s1 = g_csr[i + 1];
        size_t i0 = ((size_t)s0 * kTD + hd0) >> 1;
        size_t i1 = ((size_t)s1 * kTD + hd0) >> 1;
        float2 k0 = __half22float2(kp[i0]);
        float2 k1 = __half22float2(kp[i1]);
        float2 v0 = __half22float2(vp[i0]);
        float2 v1 = __half22float2(vp[i1]);
        float a = qv0 * k0.x + qv1 * k0.y;
        float b = qv0 * k1.x + qv1 * k1.y;
        a += __shfl_xor_sync(~0u, a, 8); b += __shfl_xor_sync(~0u, b, 8);
        a += __shfl_xor_sync(~0u, a, 4); b += __shfl_xor_sync(~0u, b, 4);
        a += __shfl_xor_sync(~0u, a, 2); b += __shfl_xor_sync(~0u, b, 2);
        a += __shfl_xor_sync(~0u, a, 1); b += __shfl_xor_sync(~0u, b, 1);
        float p0 = __expf(a), p1 = __expf(b);
        l += p0 + p1;
        acc0 += p0 * v0.x + p1 * v1.x;
        acc1 += p0 * v0.y + p1 * v1.y;
    }
    if (i < end) {
        int s0 = g_csr[i];
        size_t i0 = ((size_t)s0 * kTD + hd0) >> 1;
        float2 kk = __half22float2(kp[i0]);
        float2 vv = __half22float2(vp[i0]);
        float s = qv0 * kk.x + qv1 * kk.y;
        s += __shfl_xor_sync(~0u, s, 8);
        s += __shfl_xor_sync(~0u, s, 4);
        s += __shfl_xor_sync(~0u, s, 2);
        s += __shfl_xor_sync(~0u, s, 1);
        float p = __expf(s);
        l += p; acc0 += p * vv.x; acc1 += p * vv.y;
    }
    float inv = 1.f / l;
    aggp[outi] = __floats2half2_rn(acc0 * inv, acc1 * inv);
}

// ---------------- host ----------------
static inline void gemm(const __half* A, const __half* Bt, const float* bias,
                        float* C, __half* aux, __half* aux2,
                        int M, int N, int K, int flags) {
    dim3 g(N / BN, M / BM);
    gemm_tc<<<g, 256, DSMEM>>>(A, Bt, bias, C, aux, aux2, M, N, K, flags);
}

extern "C" void kernel_launch(void* const* d_in, const int* in_sizes, int n_in,
                              void* d_out, int out_size) {
    const float* x     = (const float*)d_in[0];
    const int*   ei    = (const int*)  d_in[1];
    const float* w_in  = (const float*)d_in[2];
    const float* b_in  = (const float*)d_in[3];
    const float* ln1_g = (const float*)d_in[4];
    const float* ln1_b = (const float*)d_in[5];
    const float* ln2_g = (const float*)d_in[6];
    const float* ln2_b = (const float*)d_in[7];
    const float* wq = (const float*)d_in[8];  const float* bq = (const float*)d_in[9];
    const float* wk = (const float*)d_in[10]; const float* bk = (const float*)d_in[11];
    const float* wv = (const float*)d_in[12]; const float* bv = (const float*)d_in[13];
    const float* wo = (const float*)d_in[14]; const float* bo = (const float*)d_in[15];
    const float* w1 = (const float*)d_in[16]; const float* b1 = (const float*)d_in[17];
    const float* w2 = (const float*)d_in[18]; const float* b2 = (const float*)d_in[19];
    float* h = (float*)d_out;

    cudaFuncSetAttribute(gemm_tc, cudaFuncAttributeMaxDynamicSharedMemorySize, DSMEM);

    __half *xh, *xnh, *kh, *vh, *aggh, *ffnh, *winT, *wqkvT, *woT, *w1T, *w2T;
    float *q, *bqkv;
    int *deg, *fill;
    cudaGetSymbolAddress((void**)&xh,    g_xh);
    cudaGetSymbolAddress((void**)&xnh,   g_xnh);
    cudaGetSymbolAddress((void**)&q,     g_q);
    cudaGetSymbolAddress((void**)&kh,    g_kh);
    cudaGetSymbolAddress((void**)&vh,    g_vh);
    cudaGetSymbolAddress((void**)&aggh,  g_aggh);
    cudaGetSymbolAddress((void**)&ffnh,  g_ffnh);
    cudaGetSymbolAddress((void**)&winT,  g_winT);
    cudaGetSymbolAddress((void**)&wqkvT, g_wqkvT);
    cudaGetSymbolAddress((void**)&woT,   g_woT);
    cudaGetSymbolAddress((void**)&w1T,   g_w1T);
    cudaGetSymbolAddress((void**)&w2T,   g_w2T);
    cudaGetSymbolAddress((void**)&bqkv,  g_bqkv);
    cudaGetSymbolAddress((void**)&deg,   g_deg);
    cudaGetSymbolAddress((void**)&fill,  g_fill);

    // ---- CSR by dst ----
    cudaMemsetAsync(deg,  0, kN * sizeof(int));
    cudaMemsetAsync(fill, 0, kN * sizeof(int));
    deg_count_kernel<<<kE / 256, 256>>>(ei);
    prefix_kernel<<<1, 1024>>>();
    scatter_kernel<<<kE / 256, 256>>>(ei);

    // ---- prep ----
    cvt_x<<<kN * kD / 4 / 256, 256>>>(x, xh);
    {
        dim3 b(32, 8);
        transpose_h<<<dim3(kD / 32, kD / 32), b>>>(w_in, winT, kD, kD);
        for (int l = 0; l < kL; ++l) {
            transpose3_h<<<dim3(kTD / 32, kD / 32, 3), b>>>(
                wq + (size_t)l * kD * kTD, wk + (size_t)l * kD * kTD, wv + (size_t)l * kD * kTD,
                wqkvT + (size_t)l * kQKV * kD, kD, kTD);
            transpose_h<<<dim3(kD / 32, kTD / 32), b>>>(wo + (size_t)l * kTD * kD,
                                                        woT + (size_t)l * kD * kTD, kTD, kD);
            transpose_h<<<dim3(kFFN / 32, kD / 32), b>>>(w1 + (size_t)l * kD * kFFN,
                                                         w1T + (size_t)l * kFFN * kD, kD, kFFN);
            transpose_h<<<dim3(kD / 32, kFFN / 32), b>>>(w2 + (size_t)l * kFFN * kD,
                                                         w2T + (size_t)l * kD * kFFN, kFFN, kD);
        }
        pack_bias<<<kL * kQKV / 256, 256>>>(bq, bk, bv);
    }

    // ---- input projection ----
    gemm(xh, winT, b_in, h, nullptr, nullptr, kN, kD, kD, 0);

    for (int l = 0; l < kL; ++l) {
        ln_kernel<<<kN, 256>>>(h, ln1_g + l * kD, ln1_b + l * kD, xnh);
        gemm(xnh, wqkvT + (size_t)l * kQKV * kD, bqkv + (size_t)l * kQKV,
             q, kh, vh, kN, kQKV, kD, 3);
        attn_kernel<<<kN, 128>>>();
        gemm(aggh, woT + (size_t)l * kD * kTD, bo + (size_t)l * kD,
             h, nullptr, nullptr, kN, kD, kTD, 1);
        ln_kernel<<<kN, 256>>>(h, ln2_g + l * kD, ln2_b + l * kD, xnh);
        gemm(xnh, w1T + (size_t)l * kFFN * kD, b1 + (size_t)l * kFFN,
             nullptr, ffnh, nullptr, kN, kFFN, kD, 2);
        gemm(ffnh, w2T + (size_t)l * kD * kFFN, b2 + (size_t)l * kD,
             h, nullptr, nullptr, kN, kD, kFFN, 1);
    }
}